// round 11
// baseline (speedup 1.0000x reference)
#include <cuda_runtime.h>
#include <cuda_bf16.h>
#include <cuda_fp16.h>
#include <mma.h>
#include <math.h>

using namespace nvcuda;

#define NMAX 100000
#define EMAX 1600000

// ---------------- static device scratch ------------------------------------
__device__ __align__(16) float  g_bufA[NMAX * 128];   // fp32 node features X
__device__ __align__(16) __half g_bufH[NMAX * 128];   // fp16 GEMM output H
__device__ int   g_col[EMAX];
__device__ int   g_rowptr[NMAX + 1];
__device__ int   g_cursor[NMAX];
__device__ int   g_outdeg[NMAX];
__device__ int   g_indeg[NMAX];
__device__ float g_norm_src[NMAX];
__device__ float g_norm_dst[NMAX];
__device__ int   g_bsums[128];
__device__ int   g_is64;
// W split bf16 hi/lo, transposed to [n][k], bases 0/16384/32768/49152
__device__ __align__(16) __nv_bfloat16 g_wt_hi[57344];
__device__ __align__(16) __nv_bfloat16 g_wt_lo[57344];

// ---------------- preprocessing ---------------------------------------------

__global__ void k_zero(const void* ei, int E, int n,
                       const float* __restrict__ W0, const float* __restrict__ W1,
                       const float* __restrict__ W2, const float* __restrict__ W3)
{
    int nodeBlocks = (n + 255) >> 8;
    int b = blockIdx.x;
    if (b < nodeBlocks) {
        int i = b * 256 + threadIdx.x;
        if (i < n) { g_outdeg[i] = 0; g_indeg[i] = 0; }
        if (b == 0 && threadIdx.x == 0) {
            const unsigned long long* p = (const unsigned long long*)ei;
            int cnt = E < 256 ? E : 256;
            int nz = 0;
            for (int k = 0; k < cnt; k++)
                if ((p[k] >> 32) != 0ULL) nz++;
            g_is64 = (nz == 0) ? 1 : 0;
        }
    } else {
        int id = (b - nodeBlocks) * 256 + threadIdx.x;
        float w; int dst;
        if (id < 49152) {
            int layer = id >> 14;
            int rem = id & 16383;
            int k = rem >> 7, nn = rem & 127;
            const float* W = layer == 0 ? W0 : (layer == 1 ? W1 : W2);
            w = W[rem];
            dst = layer * 16384 + nn * 128 + k;
        } else if (id < 57344) {
            int rem = id - 49152;
            int k = rem >> 6, nn = rem & 63;
            w = W3[rem];
            dst = 49152 + nn * 128 + k;
        } else return;
        __nv_bfloat16 h = __float2bfloat16(w);
        g_wt_hi[dst] = h;
        g_wt_lo[dst] = __float2bfloat16(w - __bfloat162float(h));
    }
}

__device__ __forceinline__ int edge_at(const void* ei, int E, int which, int e) {
    if (g_is64) return (int)((const long long*)ei)[(size_t)which * E + e];
    return ((const int*)ei)[which * E + e];
}

__global__ void k_degree(const void* __restrict__ ei, int E) {
    int e = blockIdx.x * blockDim.x + threadIdx.x;
    if (e < E) {
        atomicAdd(&g_outdeg[edge_at(ei, E, 0, e)], 1);
        atomicAdd(&g_indeg[edge_at(ei, E, 1, e)], 1);
    }
}

__global__ void k_scan_norm(int n) {
    __shared__ int s[2][1024];
    int t = threadIdx.x;
    int i = blockIdx.x * 1024 + t;
    int v = (i < n) ? g_indeg[i] : 0;
    s[0][t] = v;
    __syncthreads();
    int pin = 0;
    #pragma unroll
    for (int off = 1; off < 1024; off <<= 1) {
        int po = pin ^ 1;
        int val = s[pin][t];
        if (t >= off) val += s[pin][t - off];
        s[po][t] = val;
        __syncthreads();
        pin = po;
    }
    int incl = s[pin][t];
    if (i < n) g_rowptr[i] = incl - v;
    if (t == 1023) g_bsums[blockIdx.x] = incl;
    if (i < n) {
        int od = g_outdeg[i];
        g_norm_src[i] = od > 0 ? rsqrtf((float)od) : 0.0f;
        g_norm_dst[i] = v  > 0 ? rsqrtf((float)v)  : 0.0f;
    }
}

__global__ void k_scan_add(int n, int E) {
    __shared__ int s_off;
    int i = blockIdx.x * blockDim.x + threadIdx.x;
    if (threadIdx.x == 0) {
        int b = (blockIdx.x * blockDim.x) >> 10;
        int off = 0;
        for (int k = 0; k < b; k++) off += g_bsums[k];
        s_off = off;
    }
    __syncthreads();
    if (i < n) {
        int r = g_rowptr[i] + s_off;
        g_rowptr[i] = r;
        g_cursor[i] = r;
    }
    if (i == 0) g_rowptr[n] = E;
}

__global__ void k_fill(const void* __restrict__ ei, int E) {
    int e = blockIdx.x * blockDim.x + threadIdx.x;
    if (e < E) {
        int d = edge_at(ei, E, 1, e);
        int pos = atomicAdd(&g_cursor[d], 1);
        g_col[pos] = edge_at(ei, E, 0, e);
    }
}

// ---------------- tensor-core GEMM: H(fp16) = diag(norm_src) * X @ W --------
// Block tile 64 x DOUT (smaller M => fewer accum regs => 3 blocks/SM).
// 8 warps = 4(M, 16 rows each) x 2(N). Padded stride 40. K=128, chunks of 32.
// Product = Ah*Bh + Ah*Bl + Al*Bh, fp32 accum. Output fp16.
template <int DOUT>
__global__ void __launch_bounds__(256, 3) k_gemm_mma(
    int inSel, const float* __restrict__ Xext, int wtBase, int n)
{
    const float* __restrict__ X = (inSel == 0) ? Xext : g_bufA;
    __half* __restrict__ H = g_bufH;

    constexpr int WN = DOUT / 32;              // 4 or 2
    constexpr int AS = 40;
    __shared__ __align__(16) __nv_bfloat16 Ah[64 * AS];
    __shared__ __align__(16) __nv_bfloat16 Al[64 * AS];
    __shared__ __align__(16) __nv_bfloat16 Bh[DOUT * AS];
    __shared__ __align__(16) __nv_bfloat16 Bl[DOUT * AS];
    __shared__ __align__(16) float Stage[8 * 256];

    int tid  = threadIdx.x;
    int lane = tid & 31;
    int wrp  = tid >> 5;
    int warp_m = wrp >> 1;                     // 0..3 (16 rows each)
    int warp_n = wrp & 1;                      // 0..1
    int rows0 = blockIdx.x * 64;

    wmma::fragment<wmma::matrix_a, 16, 16, 16, __nv_bfloat16, wmma::row_major> fa_hi, fa_lo;
    wmma::fragment<wmma::matrix_b, 16, 16, 16, __nv_bfloat16, wmma::col_major> fb_hi, fb_lo;
    wmma::fragment<wmma::accumulator, 16, 16, 16, float> facc[WN];
    #pragma unroll
    for (int fn = 0; fn < WN; fn++) wmma::fill_fragment(facc[fn], 0.0f);

    // cache norm_src for the 2 rows this thread stages
    float nsc[2];
    #pragma unroll
    for (int u = 0; u < 2; u++) {
        int row = (tid + 256 * u) >> 3;
        int grow = rows0 + row;
        nsc[u] = (grow < n) ? g_norm_src[grow] : 0.0f;
    }

    const __nv_bfloat16* gh = g_wt_hi + wtBase;
    const __nv_bfloat16* gl = g_wt_lo + wtBase;

    for (int kc = 0; kc < 128; kc += 32) {
        // stage A: 64 rows x 32 k; fp32 -> bf16 hi/lo, scaled by norm_src
        #pragma unroll
        for (int u = 0; u < 2; u++) {
            int q = tid + 256 * u;             // 0..511
            int row = q >> 3;
            int kq = q & 7;
            int grow = rows0 + row;
            float4 v = make_float4(0.f, 0.f, 0.f, 0.f);
            if (grow < n) v = *(const float4*)&X[(size_t)grow * 128 + kc + kq * 4];
            float ns = nsc[u];
            float xs[4] = {v.x * ns, v.y * ns, v.z * ns, v.w * ns};
            unsigned hw[4], lw[4];
            #pragma unroll
            for (int j = 0; j < 4; j++) {
                __nv_bfloat16 h = __float2bfloat16(xs[j]);
                __nv_bfloat16 l = __float2bfloat16(xs[j] - __bfloat162float(h));
                hw[j] = (unsigned)__bfloat16_as_ushort(h);
                lw[j] = (unsigned)__bfloat16_as_ushort(l);
            }
            *(uint2*)&Ah[row * AS + kq * 4] =
                make_uint2(hw[0] | (hw[1] << 16), hw[2] | (hw[3] << 16));
            *(uint2*)&Al[row * AS + kq * 4] =
                make_uint2(lw[0] | (lw[1] << 16), lw[2] | (lw[3] << 16));
        }
        // stage B (4B copies of pre-split bf16)
        #pragma unroll
        for (int q = tid; q < DOUT * 16; q += 256) {
            int rn = q >> 4;
            int k2 = q & 15;
            ((unsigned*)Bh)[rn * (AS / 2) + k2] = ((const unsigned*)gh)[rn * 64 + (kc >> 1) + k2];
            ((unsigned*)Bl)[rn * (AS / 2) + k2] = ((const unsigned*)gl)[rn * 64 + (kc >> 1) + k2];
        }
        __syncthreads();

        #pragma unroll
        for (int kk = 0; kk < 32; kk += 16) {
            wmma::load_matrix_sync(fa_hi, &Ah[(warp_m * 16) * AS + kk], AS);
            wmma::load_matrix_sync(fa_lo, &Al[(warp_m * 16) * AS + kk], AS);
            #pragma unroll
            for (int fn = 0; fn < WN; fn++) {
                int nb = (warp_n * (DOUT / 2) + fn * 16) * AS + kk;
                wmma::load_matrix_sync(fb_hi, &Bh[nb], AS);
                wmma::load_matrix_sync(fb_lo, &Bl[nb], AS);
                wmma::mma_sync(facc[fn], fa_hi, fb_hi, facc[fn]);
                wmma::mma_sync(facc[fn], fa_hi, fb_lo, facc[fn]);
                wmma::mma_sync(facc[fn], fa_lo, fb_hi, facc[fn]);
            }
        }
        __syncthreads();
    }

    // epilogue: fp32 acc -> fp16 H via per-warp smem staging
    float* st = &Stage[wrp * 256];
    #pragma unroll
    for (int fn = 0; fn < WN; fn++) {
        wmma::store_matrix_sync(st, facc[fn], 16, wmma::mem_row_major);
        __syncwarp();
        int rbase = rows0 + warp_m * 16;
        int cbase = warp_n * (DOUT / 2) + fn * 16;
        #pragma unroll
        for (int q = lane; q < 128; q += 32) {
            int r = q >> 3, c2 = q & 7;
            int gr = rbase + r;
            if (gr < n) {
                __half2 hv = __floats2half2_rn(st[r * 16 + c2 * 2],
                                               st[r * 16 + c2 * 2 + 1]);
                *(__half2*)&H[(size_t)gr * DOUT + cbase + c2 * 2] = hv;
            }
        }
        __syncwarp();
    }
}

// ---------------- sparse aggregation (one warp per dst, fp16 gather) --------
// 4-way unrolled gather loop for load MLP.
template <int D, bool ACT>
__global__ void __launch_bounds__(256) k_agg(
    const float* __restrict__ bias, int outSel, float* __restrict__ outExt, int n)
{
    const __half* __restrict__ H = g_bufH;
    float* __restrict__ out = (outSel == 0) ? outExt : g_bufA;

    int gw = (blockIdx.x * blockDim.x + threadIdx.x) >> 5;
    int lane = threadIdx.x & 31;
    if (gw >= n) return;

    int beg = g_rowptr[gw];
    int end = g_rowptr[gw + 1];
    float4 acc = make_float4(0.f, 0.f, 0.f, 0.f);

    for (int e = beg; e < end; e += 32) {
        int m = end - e; if (m > 32) m = 32;
        int idx = (lane < m) ? g_col[e + lane] : 0;
        int j = 0;
        for (; j + 4 <= m; j += 4) {
            int s0 = __shfl_sync(0xffffffffu, idx, j);
            int s1 = __shfl_sync(0xffffffffu, idx, j + 1);
            int s2 = __shfl_sync(0xffffffffu, idx, j + 2);
            int s3 = __shfl_sync(0xffffffffu, idx, j + 3);
            if (D == 128) {
                float2 r0 = *(const float2*)&H[(size_t)s0 * 128 + lane * 4];
                float2 r1 = *(const float2*)&H[(size_t)s1 * 128 + lane * 4];
                float2 r2 = *(const float2*)&H[(size_t)s2 * 128 + lane * 4];
                float2 r3 = *(const float2*)&H[(size_t)s3 * 128 + lane * 4];
                float2 a0 = __half22float2(*(__half2*)&r0.x), b0 = __half22float2(*(__half2*)&r0.y);
                float2 a1 = __half22float2(*(__half2*)&r1.x), b1 = __half22float2(*(__half2*)&r1.y);
                float2 a2 = __half22float2(*(__half2*)&r2.x), b2 = __half22float2(*(__half2*)&r2.y);
                float2 a3 = __half22float2(*(__half2*)&r3.x), b3 = __half22float2(*(__half2*)&r3.y);
                acc.x += (a0.x + a1.x) + (a2.x + a3.x);
                acc.y += (a0.y + a1.y) + (a2.y + a3.y);
                acc.z += (b0.x + b1.x) + (b2.x + b3.x);
                acc.w += (b0.y + b1.y) + (b2.y + b3.y);
            } else {
                float2 f0 = __half22float2(*(const __half2*)&H[(size_t)s0 * 64 + lane * 2]);
                float2 f1 = __half22float2(*(const __half2*)&H[(size_t)s1 * 64 + lane * 2]);
                float2 f2 = __half22float2(*(const __half2*)&H[(size_t)s2 * 64 + lane * 2]);
                float2 f3 = __half22float2(*(const __half2*)&H[(size_t)s3 * 64 + lane * 2]);
                acc.x += (f0.x + f1.x) + (f2.x + f3.x);
                acc.y += (f0.y + f1.y) + (f2.y + f3.y);
            }
        }
        for (; j < m; j++) {
            int s0 = __shfl_sync(0xffffffffu, idx, j);
            if (D == 128) {
                float2 r0 = *(const float2*)&H[(size_t)s0 * 128 + lane * 4];
                float2 a0 = __half22float2(*(__half2*)&r0.x);
                float2 b0 = __half22float2(*(__half2*)&r0.y);
                acc.x += a0.x; acc.y += a0.y; acc.z += b0.x; acc.w += b0.y;
            } else {
                float2 f0 = __half22float2(*(const __half2*)&H[(size_t)s0 * 64 + lane * 2]);
                acc.x += f0.x; acc.y += f0.y;
            }
        }
    }

    float nd = g_norm_dst[gw];
    if (D == 128) {
        float4 bb = *(const float4*)&bias[lane * 4];
        float4 r;
        r.x = fmaf(acc.x, nd, bb.x);
        r.y = fmaf(acc.y, nd, bb.y);
        r.z = fmaf(acc.z, nd, bb.z);
        r.w = fmaf(acc.w, nd, bb.w);
        if (ACT) { r.x = tanhf(r.x); r.y = tanhf(r.y);
                   r.z = tanhf(r.z); r.w = tanhf(r.w); }
        *(float4*)&out[(size_t)gw * 128 + lane * 4] = r;
    } else {
        float2 bb = *(const float2*)&bias[lane * 2];
        float2 r;
        r.x = fmaf(acc.x, nd, bb.x);
        r.y = fmaf(acc.y, nd, bb.y);
        if (ACT) { r.x = tanhf(r.x); r.y = tanhf(r.y); }
        *(float2*)&out[(size_t)gw * 64 + lane * 2] = r;
    }
}

// ---------------- launch ----------------------------------------------------

extern "C" void kernel_launch(void* const* d_in, const int* in_sizes, int n_in,
                              void* d_out, int out_size)
{
    const float* feat = (const float*)d_in[0];
    const void*  ei   = d_in[1];
    const float* W0 = (const float*)d_in[2]; const float* b0 = (const float*)d_in[3];
    const float* W1 = (const float*)d_in[4]; const float* b1 = (const float*)d_in[5];
    const float* W2 = (const float*)d_in[6]; const float* b2 = (const float*)d_in[7];
    const float* W3 = (const float*)d_in[8]; const float* b3 = (const float*)d_in[9];

    int N = in_sizes[0] / 128;
    int E = in_sizes[1] / 2;
    float* out = (float*)d_out;

    int nodeBlocks = (N + 255) / 256;
    int wBlocks = (57344 + 255) / 256;

    k_zero     <<<nodeBlocks + wBlocks, 256>>>(ei, E, N, W0, W1, W2, W3);
    k_degree   <<<(E + 255) / 256, 256>>>(ei, E);
    k_scan_norm<<<(N + 1023) / 1024, 1024>>>(N);

    int gemmGrid = (N + 63) / 64;
    int aggGrid  = (N * 32 + 255) / 256;

    // #4: layer-0 GEMM (profiled launch)
    k_gemm_mma<128><<<gemmGrid, 256>>>(0, feat, 0, N);

    // #5,#6: finish CSR (only k_agg needs it)
    k_scan_add<<<(N + 255) / 256, 256>>>(N, E);
    k_fill    <<<(E + 255) / 256, 256>>>(ei, E);

    // remaining layers
    k_agg<128, true><<<aggGrid, 256>>>(b0, 1, nullptr, N);
    k_gemm_mma<128><<<gemmGrid, 256>>>(1, nullptr, 16384, N);
    k_agg<128, true><<<aggGrid, 256>>>(b1, 1, nullptr, N);
    k_gemm_mma<128><<<gemmGrid, 256>>>(1, nullptr, 32768, N);
    k_agg<128, true><<<aggGrid, 256>>>(b2, 1, nullptr, N);
    k_gemm_mma<64><<<gemmGrid, 256>>>(1, nullptr, 49152, N);
    k_agg<64, false><<<aggGrid, 256>>>(b3, 0, out, N);
}

// round 12
// speedup vs baseline: 1.0441x; 1.0441x over previous
#include <cuda_runtime.h>
#include <cuda_bf16.h>
#include <cuda_fp16.h>
#include <mma.h>
#include <math.h>

using namespace nvcuda;

#define NMAX 100000
#define EMAX 1600000

// ---------------- static device scratch ------------------------------------
__device__ __align__(16) float  g_bufA[NMAX * 128];   // fp32 node features X
__device__ __align__(16) __half g_bufH[NMAX * 128];   // fp16 GEMM output H
__device__ int   g_col[EMAX];
__device__ int   g_rowptr[NMAX + 1];
__device__ int   g_cursor[NMAX];
__device__ int   g_outdeg[NMAX];
__device__ int   g_indeg[NMAX];
__device__ float g_norm_src[NMAX];
__device__ float g_norm_dst[NMAX];
__device__ int   g_bsums[128];
__device__ int   g_is64;
// W split bf16 hi/lo, transposed to [n][k], bases 0/16384/32768/49152
__device__ __align__(16) __nv_bfloat16 g_wt_hi[57344];
__device__ __align__(16) __nv_bfloat16 g_wt_lo[57344];

// ---------------- preprocessing ---------------------------------------------

__global__ void k_zero(const void* ei, int E, int n,
                       const float* __restrict__ W0, const float* __restrict__ W1,
                       const float* __restrict__ W2, const float* __restrict__ W3)
{
    int nodeBlocks = (n + 255) >> 8;
    int b = blockIdx.x;
    if (b < nodeBlocks) {
        int i = b * 256 + threadIdx.x;
        if (i < n) { g_outdeg[i] = 0; g_indeg[i] = 0; }
        if (b == 0 && threadIdx.x == 0) {
            const unsigned long long* p = (const unsigned long long*)ei;
            int cnt = E < 256 ? E : 256;
            int nz = 0;
            for (int k = 0; k < cnt; k++)
                if ((p[k] >> 32) != 0ULL) nz++;
            g_is64 = (nz == 0) ? 1 : 0;
        }
    } else {
        int id = (b - nodeBlocks) * 256 + threadIdx.x;
        float w; int dst;
        if (id < 49152) {
            int layer = id >> 14;
            int rem = id & 16383;
            int k = rem >> 7, nn = rem & 127;
            const float* W = layer == 0 ? W0 : (layer == 1 ? W1 : W2);
            w = W[rem];
            dst = layer * 16384 + nn * 128 + k;
        } else if (id < 57344) {
            int rem = id - 49152;
            int k = rem >> 6, nn = rem & 63;
            w = W3[rem];
            dst = 49152 + nn * 128 + k;
        } else return;
        __nv_bfloat16 h = __float2bfloat16(w);
        g_wt_hi[dst] = h;
        g_wt_lo[dst] = __float2bfloat16(w - __bfloat162float(h));
    }
}

__device__ __forceinline__ int edge_at(const void* ei, int E, int which, int e) {
    if (g_is64) return (int)((const long long*)ei)[(size_t)which * E + e];
    return ((const int*)ei)[which * E + e];
}

__global__ void k_degree(const void* __restrict__ ei, int E) {
    int e = blockIdx.x * blockDim.x + threadIdx.x;
    if (e < E) {
        atomicAdd(&g_outdeg[edge_at(ei, E, 0, e)], 1);
        atomicAdd(&g_indeg[edge_at(ei, E, 1, e)], 1);
    }
}

__global__ void k_scan_norm(int n) {
    __shared__ int s[2][1024];
    int t = threadIdx.x;
    int i = blockIdx.x * 1024 + t;
    int v = (i < n) ? g_indeg[i] : 0;
    s[0][t] = v;
    __syncthreads();
    int pin = 0;
    #pragma unroll
    for (int off = 1; off < 1024; off <<= 1) {
        int po = pin ^ 1;
        int val = s[pin][t];
        if (t >= off) val += s[pin][t - off];
        s[po][t] = val;
        __syncthreads();
        pin = po;
    }
    int incl = s[pin][t];
    if (i < n) g_rowptr[i] = incl - v;
    if (t == 1023) g_bsums[blockIdx.x] = incl;
    if (i < n) {
        int od = g_outdeg[i];
        g_norm_src[i] = od > 0 ? rsqrtf((float)od) : 0.0f;
        g_norm_dst[i] = v  > 0 ? rsqrtf((float)v)  : 0.0f;
    }
}

__global__ void k_scan_add(int n, int E) {
    __shared__ int s_off;
    int i = blockIdx.x * blockDim.x + threadIdx.x;
    if (threadIdx.x == 0) {
        int b = (blockIdx.x * blockDim.x) >> 10;
        int off = 0;
        for (int k = 0; k < b; k++) off += g_bsums[k];
        s_off = off;
    }
    __syncthreads();
    if (i < n) {
        int r = g_rowptr[i] + s_off;
        g_rowptr[i] = r;
        g_cursor[i] = r;
    }
    if (i == 0) g_rowptr[n] = E;
}

__global__ void k_fill(const void* __restrict__ ei, int E) {
    int e = blockIdx.x * blockDim.x + threadIdx.x;
    if (e < E) {
        int d = edge_at(ei, E, 1, e);
        int pos = atomicAdd(&g_cursor[d], 1);
        g_col[pos] = edge_at(ei, E, 0, e);
    }
}

// ---------------- tensor-core GEMM: H(fp16) = diag(norm_src) * X @ W --------
// R8 configuration (best measured): block tile 128 x DOUT, K chunks of 32,
// 8 warps = 4(M) x 2(N), padded smem stride 40, 2 blocks/SM.
// Product = Ah*Bh + Ah*Bl + Al*Bh, fp32 accum. Output fp16.
template <int DOUT>
__global__ void __launch_bounds__(256, 2) k_gemm_mma(
    int inSel, const float* __restrict__ Xext, int wtBase, int n)
{
    const float* __restrict__ X = (inSel == 0) ? Xext : g_bufA;
    __half* __restrict__ H = g_bufH;

    constexpr int WN = DOUT / 32;
    constexpr int AS = 40;
    __shared__ __align__(16) __nv_bfloat16 Ah[128 * AS];
    __shared__ __align__(16) __nv_bfloat16 Al[128 * AS];
    __shared__ __align__(16) __nv_bfloat16 Bh[DOUT * AS];
    __shared__ __align__(16) __nv_bfloat16 Bl[DOUT * AS];
    __shared__ __align__(16) float Stage[8 * 256];

    int tid  = threadIdx.x;
    int lane = tid & 31;
    int wrp  = tid >> 5;
    int warp_m = wrp >> 1;
    int warp_n = wrp & 1;
    int rows0 = blockIdx.x * 128;

    wmma::fragment<wmma::matrix_a, 16, 16, 16, __nv_bfloat16, wmma::row_major> fa_hi[2], fa_lo[2];
    wmma::fragment<wmma::matrix_b, 16, 16, 16, __nv_bfloat16, wmma::col_major> fb_hi, fb_lo;
    wmma::fragment<wmma::accumulator, 16, 16, 16, float> facc[2][WN];
    #pragma unroll
    for (int fm = 0; fm < 2; fm++)
        #pragma unroll
        for (int fn = 0; fn < WN; fn++) wmma::fill_fragment(facc[fm][fn], 0.0f);

    const __nv_bfloat16* gh = g_wt_hi + wtBase;
    const __nv_bfloat16* gl = g_wt_lo + wtBase;

    for (int kc = 0; kc < 128; kc += 32) {
        // stage A: fp32 -> bf16 hi/lo, scaled by norm_src; 8B packed stores
        #pragma unroll
        for (int u = 0; u < 4; u++) {
            int q = tid + 256 * u;
            int row = q >> 3;
            int kq = q & 7;
            int grow = rows0 + row;
            float4 v = make_float4(0.f, 0.f, 0.f, 0.f);
            float ns = 0.f;
            if (grow < n) {
                ns = g_norm_src[grow];
                v = *(const float4*)&X[(size_t)grow * 128 + kc + kq * 4];
            }
            float xs[4] = {v.x * ns, v.y * ns, v.z * ns, v.w * ns};
            unsigned hw[4], lw[4];
            #pragma unroll
            for (int j = 0; j < 4; j++) {
                __nv_bfloat16 h = __float2bfloat16(xs[j]);
                __nv_bfloat16 l = __float2bfloat16(xs[j] - __bfloat162float(h));
                hw[j] = (unsigned)__bfloat16_as_ushort(h);
                lw[j] = (unsigned)__bfloat16_as_ushort(l);
            }
            *(uint2*)&Ah[row * AS + kq * 4] =
                make_uint2(hw[0] | (hw[1] << 16), hw[2] | (hw[3] << 16));
            *(uint2*)&Al[row * AS + kq * 4] =
                make_uint2(lw[0] | (lw[1] << 16), lw[2] | (lw[3] << 16));
        }
        // stage B (4B copies of pre-split bf16)
        for (int q = tid; q < DOUT * 16; q += 256) {
            int rn = q >> 4;
            int k2 = q & 15;
            ((unsigned*)Bh)[rn * (AS / 2) + k2] = ((const unsigned*)gh)[rn * 64 + (kc >> 1) + k2];
            ((unsigned*)Bl)[rn * (AS / 2) + k2] = ((const unsigned*)gl)[rn * 64 + (kc >> 1) + k2];
        }
        __syncthreads();

        #pragma unroll
        for (int kk = 0; kk < 32; kk += 16) {
            #pragma unroll
            for (int fm = 0; fm < 2; fm++) {
                wmma::load_matrix_sync(fa_hi[fm], &Ah[(warp_m * 32 + fm * 16) * AS + kk], AS);
                wmma::load_matrix_sync(fa_lo[fm], &Al[(warp_m * 32 + fm * 16) * AS + kk], AS);
            }
            #pragma unroll
            for (int fn = 0; fn < WN; fn++) {
                int nb = (warp_n * (DOUT / 2) + fn * 16) * AS + kk;
                wmma::load_matrix_sync(fb_hi, &Bh[nb], AS);
                wmma::load_matrix_sync(fb_lo, &Bl[nb], AS);
                #pragma unroll
                for (int fm = 0; fm < 2; fm++) {
                    wmma::mma_sync(facc[fm][fn], fa_hi[fm], fb_hi, facc[fm][fn]);
                    wmma::mma_sync(facc[fm][fn], fa_hi[fm], fb_lo, facc[fm][fn]);
                    wmma::mma_sync(facc[fm][fn], fa_lo[fm], fb_hi, facc[fm][fn]);
                }
            }
        }
        __syncthreads();
    }

    // epilogue: fp32 acc -> fp16 H via per-warp smem staging
    float* st = &Stage[wrp * 256];
    #pragma unroll
    for (int fm = 0; fm < 2; fm++)
        #pragma unroll
        for (int fn = 0; fn < WN; fn++) {
            wmma::store_matrix_sync(st, facc[fm][fn], 16, wmma::mem_row_major);
            __syncwarp();
            int rbase = rows0 + warp_m * 32 + fm * 16;
            int cbase = warp_n * (DOUT / 2) + fn * 16;
            #pragma unroll
            for (int q = lane; q < 128; q += 32) {
                int r = q >> 3, c2 = q & 7;
                int gr = rbase + r;
                if (gr < n) {
                    __half2 hv = __floats2half2_rn(st[r * 16 + c2 * 2],
                                                   st[r * 16 + c2 * 2 + 1]);
                    *(__half2*)&H[(size_t)gr * DOUT + cbase + c2 * 2] = hv;
                }
            }
            __syncwarp();
        }
}

// ---------------- sparse aggregation (one warp per dst, fp16 gather) --------
// 4-way unrolled gather loop (validated ~10us total win in R11).
template <int D, bool ACT>
__global__ void __launch_bounds__(256) k_agg(
    const float* __restrict__ bias, int outSel, float* __restrict__ outExt, int n)
{
    const __half* __restrict__ H = g_bufH;
    float* __restrict__ out = (outSel == 0) ? outExt : g_bufA;

    int gw = (blockIdx.x * blockDim.x + threadIdx.x) >> 5;
    int lane = threadIdx.x & 31;
    if (gw >= n) return;

    int beg = g_rowptr[gw];
    int end = g_rowptr[gw + 1];
    float4 acc = make_float4(0.f, 0.f, 0.f, 0.f);

    for (int e = beg; e < end; e += 32) {
        int m = end - e; if (m > 32) m = 32;
        int idx = (lane < m) ? g_col[e + lane] : 0;
        int j = 0;
        for (; j + 4 <= m; j += 4) {
            int s0 = __shfl_sync(0xffffffffu, idx, j);
            int s1 = __shfl_sync(0xffffffffu, idx, j + 1);
            int s2 = __shfl_sync(0xffffffffu, idx, j + 2);
            int s3 = __shfl_sync(0xffffffffu, idx, j + 3);
            if (D == 128) {
                float2 r0 = *(const float2*)&H[(size_t)s0 * 128 + lane * 4];
                float2 r1 = *(const float2*)&H[(size_t)s1 * 128 + lane * 4];
                float2 r2 = *(const float2*)&H[(size_t)s2 * 128 + lane * 4];
                float2 r3 = *(const float2*)&H[(size_t)s3 * 128 + lane * 4];
                float2 a0 = __half22float2(*(__half2*)&r0.x), b0 = __half22float2(*(__half2*)&r0.y);
                float2 a1 = __half22float2(*(__half2*)&r1.x), b1 = __half22float2(*(__half2*)&r1.y);
                float2 a2 = __half22float2(*(__half2*)&r2.x), b2 = __half22float2(*(__half2*)&r2.y);
                float2 a3 = __half22float2(*(__half2*)&r3.x), b3 = __half22float2(*(__half2*)&r3.y);
                acc.x += (a0.x + a1.x) + (a2.x + a3.x);
                acc.y += (a0.y + a1.y) + (a2.y + a3.y);
                acc.z += (b0.x + b1.x) + (b2.x + b3.x);
                acc.w += (b0.y + b1.y) + (b2.y + b3.y);
            } else {
                float2 f0 = __half22float2(*(const __half2*)&H[(size_t)s0 * 64 + lane * 2]);
                float2 f1 = __half22float2(*(const __half2*)&H[(size_t)s1 * 64 + lane * 2]);
                float2 f2 = __half22float2(*(const __half2*)&H[(size_t)s2 * 64 + lane * 2]);
                float2 f3 = __half22float2(*(const __half2*)&H[(size_t)s3 * 64 + lane * 2]);
                acc.x += (f0.x + f1.x) + (f2.x + f3.x);
                acc.y += (f0.y + f1.y) + (f2.y + f3.y);
            }
        }
        for (; j < m; j++) {
            int s0 = __shfl_sync(0xffffffffu, idx, j);
            if (D == 128) {
                float2 r0 = *(const float2*)&H[(size_t)s0 * 128 + lane * 4];
                float2 a0 = __half22float2(*(__half2*)&r0.x);
                float2 b0 = __half22float2(*(__half2*)&r0.y);
                acc.x += a0.x; acc.y += a0.y; acc.z += b0.x; acc.w += b0.y;
            } else {
                float2 f0 = __half22float2(*(const __half2*)&H[(size_t)s0 * 64 + lane * 2]);
                acc.x += f0.x; acc.y += f0.y;
            }
        }
    }

    float nd = g_norm_dst[gw];
    if (D == 128) {
        float4 bb = *(const float4*)&bias[lane * 4];
        float4 r;
        r.x = fmaf(acc.x, nd, bb.x);
        r.y = fmaf(acc.y, nd, bb.y);
        r.z = fmaf(acc.z, nd, bb.z);
        r.w = fmaf(acc.w, nd, bb.w);
        if (ACT) { r.x = tanhf(r.x); r.y = tanhf(r.y);
                   r.z = tanhf(r.z); r.w = tanhf(r.w); }
        *(float4*)&out[(size_t)gw * 128 + lane * 4] = r;
    } else {
        float2 bb = *(const float2*)&bias[lane * 2];
        float2 r;
        r.x = fmaf(acc.x, nd, bb.x);
        r.y = fmaf(acc.y, nd, bb.y);
        if (ACT) { r.x = tanhf(r.x); r.y = tanhf(r.y); }
        *(float2*)&out[(size_t)gw * 64 + lane * 2] = r;
    }
}

// ---------------- launch ----------------------------------------------------

extern "C" void kernel_launch(void* const* d_in, const int* in_sizes, int n_in,
                              void* d_out, int out_size)
{
    const float* feat = (const float*)d_in[0];
    const void*  ei   = d_in[1];
    const float* W0 = (const float*)d_in[2]; const float* b0 = (const float*)d_in[3];
    const float* W1 = (const float*)d_in[4]; const float* b1 = (const float*)d_in[5];
    const float* W2 = (const float*)d_in[6]; const float* b2 = (const float*)d_in[7];
    const float* W3 = (const float*)d_in[8]; const float* b3 = (const float*)d_in[9];

    int N = in_sizes[0] / 128;
    int E = in_sizes[1] / 2;
    float* out = (float*)d_out;

    int nodeBlocks = (N + 255) / 256;
    int wBlocks = (57344 + 255) / 256;

    k_zero     <<<nodeBlocks + wBlocks, 256>>>(ei, E, N, W0, W1, W2, W3);
    k_degree   <<<(E + 255) / 256, 256>>>(ei, E);
    k_scan_norm<<<(N + 1023) / 1024, 1024>>>(N);

    int gemmGrid = (N + 127) / 128;
    int aggGrid  = (N * 32 + 255) / 256;

    // #4: layer-0 GEMM (profiled launch)
    k_gemm_mma<128><<<gemmGrid, 256>>>(0, feat, 0, N);

    // #5,#6: finish CSR (only k_agg needs it)
    k_scan_add<<<(N + 255) / 256, 256>>>(N, E);
    k_fill    <<<(E + 255) / 256, 256>>>(ei, E);

    // remaining layers
    k_agg<128, true><<<aggGrid, 256>>>(b0, 1, nullptr, N);
    k_gemm_mma<128><<<gemmGrid, 256>>>(1, nullptr, 16384, N);
    k_agg<128, true><<<aggGrid, 256>>>(b1, 1, nullptr, N);
    k_gemm_mma<128><<<gemmGrid, 256>>>(1, nullptr, 32768, N);
    k_agg<128, true><<<aggGrid, 256>>>(b2, 1, nullptr, N);
    k_gemm_mma<64><<<gemmGrid, 256>>>(1, nullptr, 49152, N);
    k_agg<64, false><<<aggGrid, 256>>>(b3, 0, out, N);
}

// round 13
// speedup vs baseline: 1.1810x; 1.1311x over previous
#include <cuda_runtime.h>
#include <cuda_bf16.h>
#include <cuda_fp16.h>
#include <mma.h>
#include <math.h>

using namespace nvcuda;

#define NMAX 100000
#define EMAX 1600000

// ---------------- static device scratch ------------------------------------
__device__ __align__(16) __half g_xa[NMAX * 128];     // fp16 X (prescaled by norm_src), layers 1-3
__device__ __align__(16) __half g_bufH[NMAX * 128];   // fp16 GEMM output H (gather source)
__device__ int   g_col[EMAX];
__device__ int   g_rowptr[NMAX + 1];
__device__ int   g_cursor[NMAX];
__device__ int   g_outdeg[NMAX];
__device__ int   g_indeg[NMAX];
__device__ float g_norm_src[NMAX];
__device__ float g_norm_dst[NMAX];
__device__ int   g_bsums[128];
__device__ int   g_is64;
// W split fp16 hi/lo, transposed to [n][k], bases 0/16384/32768/49152
__device__ __align__(16) __half g_wt_hi[57344];
__device__ __align__(16) __half g_wt_lo[57344];

// ---------------- preprocessing ---------------------------------------------

__global__ void k_zero(const void* ei, int E, int n,
                       const float* __restrict__ W0, const float* __restrict__ W1,
                       const float* __restrict__ W2, const float* __restrict__ W3)
{
    int nodeBlocks = (n + 255) >> 8;
    int b = blockIdx.x;
    if (b < nodeBlocks) {
        int i = b * 256 + threadIdx.x;
        if (i < n) { g_outdeg[i] = 0; g_indeg[i] = 0; }
        if (b == 0 && threadIdx.x == 0) {
            const unsigned long long* p = (const unsigned long long*)ei;
            int cnt = E < 256 ? E : 256;
            int nz = 0;
            for (int k = 0; k < cnt; k++)
                if ((p[k] >> 32) != 0ULL) nz++;
            g_is64 = (nz == 0) ? 1 : 0;
        }
    } else {
        int id = (b - nodeBlocks) * 256 + threadIdx.x;
        float w; int dst;
        if (id < 49152) {
            int layer = id >> 14;
            int rem = id & 16383;
            int k = rem >> 7, nn = rem & 127;
            const float* W = layer == 0 ? W0 : (layer == 1 ? W1 : W2);
            w = W[rem];
            dst = layer * 16384 + nn * 128 + k;
        } else if (id < 57344) {
            int rem = id - 49152;
            int k = rem >> 6, nn = rem & 63;
            w = W3[rem];
            dst = 49152 + nn * 128 + k;
        } else return;
        __half h = __float2half(w);
        g_wt_hi[dst] = h;
        g_wt_lo[dst] = __float2half(w - __half2float(h));
    }
}

__device__ __forceinline__ int edge_at(const void* ei, int E, int which, int e) {
    if (g_is64) return (int)((const long long*)ei)[(size_t)which * E + e];
    return ((const int*)ei)[which * E + e];
}

__global__ void k_degree(const void* __restrict__ ei, int E) {
    int e = blockIdx.x * blockDim.x + threadIdx.x;
    if (e < E) {
        atomicAdd(&g_outdeg[edge_at(ei, E, 0, e)], 1);
        atomicAdd(&g_indeg[edge_at(ei, E, 1, e)], 1);
    }
}

__global__ void k_scan_norm(int n) {
    __shared__ int s[2][1024];
    int t = threadIdx.x;
    int i = blockIdx.x * 1024 + t;
    int v = (i < n) ? g_indeg[i] : 0;
    s[0][t] = v;
    __syncthreads();
    int pin = 0;
    #pragma unroll
    for (int off = 1; off < 1024; off <<= 1) {
        int po = pin ^ 1;
        int val = s[pin][t];
        if (t >= off) val += s[pin][t - off];
        s[po][t] = val;
        __syncthreads();
        pin = po;
    }
    int incl = s[pin][t];
    if (i < n) g_rowptr[i] = incl - v;
    if (t == 1023) g_bsums[blockIdx.x] = incl;
    if (i < n) {
        int od = g_outdeg[i];
        g_norm_src[i] = od > 0 ? rsqrtf((float)od) : 0.0f;
        g_norm_dst[i] = v  > 0 ? rsqrtf((float)v)  : 0.0f;
    }
}

__global__ void k_scan_add(int n, int E) {
    __shared__ int s_off;
    int i = blockIdx.x * blockDim.x + threadIdx.x;
    if (threadIdx.x == 0) {
        int b = (blockIdx.x * blockDim.x) >> 10;
        int off = 0;
        for (int k = 0; k < b; k++) off += g_bsums[k];
        s_off = off;
    }
    __syncthreads();
    if (i < n) {
        int r = g_rowptr[i] + s_off;
        g_rowptr[i] = r;
        g_cursor[i] = r;
    }
    if (i == 0) g_rowptr[n] = E;
}

__global__ void k_fill(const void* __restrict__ ei, int E) {
    int e = blockIdx.x * blockDim.x + threadIdx.x;
    if (e < E) {
        int d = edge_at(ei, E, 1, e);
        int pos = atomicAdd(&g_cursor[d], 1);
        g_col[pos] = edge_at(ei, E, 0, e);
    }
}

// ---------------- tensor-core GEMM: H(fp16) = A @ (Wh + Wl) ------------------
// A fp16 (prescaled by norm_src); W fp16 hi/lo => 2 MMAs per tile, fp32 accum.
// CONV=true : A converted from fp32 feat at staging (layer 0)
// CONV=false: A = g_xa (pre-converted by previous k_agg), pure copies
// Block tile 128 x DOUT; 8 warps = 4(M) x 2(N); padded stride 40; 2 blocks/SM.
template <int DOUT, bool CONV>
__global__ void __launch_bounds__(256, 2) k_gemm_mma(
    const float* __restrict__ Xext, int wtBase, int n)
{
    __half* __restrict__ H = g_bufH;

    constexpr int WN = DOUT / 32;
    constexpr int AS = 40;
    __shared__ __align__(16) __half Ax[128 * AS];
    __shared__ __align__(16) __half Bh[DOUT * AS];
    __shared__ __align__(16) __half Bl[DOUT * AS];
    __shared__ __align__(16) float Stage[8 * 256];

    int tid  = threadIdx.x;
    int lane = tid & 31;
    int wrp  = tid >> 5;
    int warp_m = wrp >> 1;
    int warp_n = wrp & 1;
    int rows0 = blockIdx.x * 128;

    wmma::fragment<wmma::matrix_a, 16, 16, 16, __half, wmma::row_major> fa[2];
    wmma::fragment<wmma::matrix_b, 16, 16, 16, __half, wmma::col_major> fb_hi, fb_lo;
    wmma::fragment<wmma::accumulator, 16, 16, 16, float> facc[2][WN];
    #pragma unroll
    for (int fm = 0; fm < 2; fm++)
        #pragma unroll
        for (int fn = 0; fn < WN; fn++) wmma::fill_fragment(facc[fm][fn], 0.0f);

    const __half* gh = g_wt_hi + wtBase;
    const __half* gl = g_wt_lo + wtBase;

    for (int kc = 0; kc < 128; kc += 32) {
        if (CONV) {
            // fp32 feat -> fp16, scaled by norm_src; 8B packed stores
            #pragma unroll
            for (int u = 0; u < 4; u++) {
                int q = tid + 256 * u;         // 0..1023
                int row = q >> 3;
                int kq = q & 7;
                int grow = rows0 + row;
                float4 v = make_float4(0.f, 0.f, 0.f, 0.f);
                float ns = 0.f;
                if (grow < n) {
                    ns = g_norm_src[grow];
                    v = *(const float4*)&Xext[(size_t)grow * 128 + kc + kq * 4];
                }
                __half2 p0 = __floats2half2_rn(v.x * ns, v.y * ns);
                __half2 p1 = __floats2half2_rn(v.z * ns, v.w * ns);
                *(uint2*)&Ax[row * AS + kq * 4] =
                    make_uint2(*(unsigned*)&p0, *(unsigned*)&p1);
            }
        } else {
            // pure 16B copies of pre-converted fp16 A
            #pragma unroll
            for (int u = 0; u < 2; u++) {
                int q = tid + 256 * u;         // 0..511
                int row = q >> 2;
                int kq = q & 3;
                int grow = rows0 + row;
                uint4 v = make_uint4(0u, 0u, 0u, 0u);
                if (grow < n)
                    v = *(const uint4*)&g_xa[(size_t)grow * 128 + kc + kq * 8];
                *(uint4*)&Ax[row * AS + kq * 8] = v;
            }
        }
        // stage B (4B copies of pre-split fp16)
        for (int q = tid; q < DOUT * 16; q += 256) {
            int rn = q >> 4;
            int k2 = q & 15;
            ((unsigned*)Bh)[rn * (AS / 2) + k2] = ((const unsigned*)gh)[rn * 64 + (kc >> 1) + k2];
            ((unsigned*)Bl)[rn * (AS / 2) + k2] = ((const unsigned*)gl)[rn * 64 + (kc >> 1) + k2];
        }
        __syncthreads();

        #pragma unroll
        for (int kk = 0; kk < 32; kk += 16) {
            #pragma unroll
            for (int fm = 0; fm < 2; fm++)
                wmma::load_matrix_sync(fa[fm], &Ax[(warp_m * 32 + fm * 16) * AS + kk], AS);
            #pragma unroll
            for (int fn = 0; fn < WN; fn++) {
                int nb = (warp_n * (DOUT / 2) + fn * 16) * AS + kk;
                wmma::load_matrix_sync(fb_hi, &Bh[nb], AS);
                wmma::load_matrix_sync(fb_lo, &Bl[nb], AS);
                #pragma unroll
                for (int fm = 0; fm < 2; fm++) {
                    wmma::mma_sync(facc[fm][fn], fa[fm], fb_hi, facc[fm][fn]);
                    wmma::mma_sync(facc[fm][fn], fa[fm], fb_lo, facc[fm][fn]);
                }
            }
        }
        __syncthreads();
    }

    // epilogue: fp32 acc -> fp16 H via per-warp smem staging
    float* st = &Stage[wrp * 256];
    #pragma unroll
    for (int fm = 0; fm < 2; fm++)
        #pragma unroll
        for (int fn = 0; fn < WN; fn++) {
            wmma::store_matrix_sync(st, facc[fm][fn], 16, wmma::mem_row_major);
            __syncwarp();
            int rbase = rows0 + warp_m * 32 + fm * 16;
            int cbase = warp_n * (DOUT / 2) + fn * 16;
            #pragma unroll
            for (int q = lane; q < 128; q += 32) {
                int r = q >> 3, c2 = q & 7;
                int gr = rbase + r;
                if (gr < n) {
                    __half2 hv = __floats2half2_rn(st[r * 16 + c2 * 2],
                                                   st[r * 16 + c2 * 2 + 1]);
                    *(__half2*)&H[(size_t)gr * DOUT + cbase + c2 * 2] = hv;
                }
            }
            __syncwarp();
        }
}

// ---------------- sparse aggregation (one warp per dst, fp16 gather) --------
// 4-way unrolled gather loop.
// TOX=true : emit prescaled fp16 X to g_xa (layers 0-2)
// TOX=false: emit fp32 to outExt (final layer)
template <int D, bool ACT, bool TOX>
__global__ void __launch_bounds__(256) k_agg(
    const float* __restrict__ bias, float* __restrict__ outExt, int n)
{
    const __half* __restrict__ H = g_bufH;

    int gw = (blockIdx.x * blockDim.x + threadIdx.x) >> 5;
    int lane = threadIdx.x & 31;
    if (gw >= n) return;

    int beg = g_rowptr[gw];
    int end = g_rowptr[gw + 1];
    float4 acc = make_float4(0.f, 0.f, 0.f, 0.f);

    for (int e = beg; e < end; e += 32) {
        int m = end - e; if (m > 32) m = 32;
        int idx = (lane < m) ? g_col[e + lane] : 0;
        int j = 0;
        for (; j + 4 <= m; j += 4) {
            int s0 = __shfl_sync(0xffffffffu, idx, j);
            int s1 = __shfl_sync(0xffffffffu, idx, j + 1);
            int s2 = __shfl_sync(0xffffffffu, idx, j + 2);
            int s3 = __shfl_sync(0xffffffffu, idx, j + 3);
            if (D == 128) {
                float2 r0 = *(const float2*)&H[(size_t)s0 * 128 + lane * 4];
                float2 r1 = *(const float2*)&H[(size_t)s1 * 128 + lane * 4];
                float2 r2 = *(const float2*)&H[(size_t)s2 * 128 + lane * 4];
                float2 r3 = *(const float2*)&H[(size_t)s3 * 128 + lane * 4];
                float2 a0 = __half22float2(*(__half2*)&r0.x), b0 = __half22float2(*(__half2*)&r0.y);
                float2 a1 = __half22float2(*(__half2*)&r1.x), b1 = __half22float2(*(__half2*)&r1.y);
                float2 a2 = __half22float2(*(__half2*)&r2.x), b2 = __half22float2(*(__half2*)&r2.y);
                float2 a3 = __half22float2(*(__half2*)&r3.x), b3 = __half22float2(*(__half2*)&r3.y);
                acc.x += (a0.x + a1.x) + (a2.x + a3.x);
                acc.y += (a0.y + a1.y) + (a2.y + a3.y);
                acc.z += (b0.x + b1.x) + (b2.x + b3.x);
                acc.w += (b0.y + b1.y) + (b2.y + b3.y);
            } else {
                float2 f0 = __half22float2(*(const __half2*)&H[(size_t)s0 * 64 + lane * 2]);
                float2 f1 = __half22float2(*(const __half2*)&H[(size_t)s1 * 64 + lane * 2]);
                float2 f2 = __half22float2(*(const __half2*)&H[(size_t)s2 * 64 + lane * 2]);
                float2 f3 = __half22float2(*(const __half2*)&H[(size_t)s3 * 64 + lane * 2]);
                acc.x += (f0.x + f1.x) + (f2.x + f3.x);
                acc.y += (f0.y + f1.y) + (f2.y + f3.y);
            }
        }
        for (; j < m; j++) {
            int s0 = __shfl_sync(0xffffffffu, idx, j);
            if (D == 128) {
                float2 r0 = *(const float2*)&H[(size_t)s0 * 128 + lane * 4];
                float2 a0 = __half22float2(*(__half2*)&r0.x);
                float2 b0 = __half22float2(*(__half2*)&r0.y);
                acc.x += a0.x; acc.y += a0.y; acc.z += b0.x; acc.w += b0.y;
            } else {
                float2 f0 = __half22float2(*(const __half2*)&H[(size_t)s0 * 64 + lane * 2]);
                acc.x += f0.x; acc.y += f0.y;
            }
        }
    }

    float nd = g_norm_dst[gw];
    if (D == 128) {
        float4 bb = *(const float4*)&bias[lane * 4];
        float4 r;
        r.x = fmaf(acc.x, nd, bb.x);
        r.y = fmaf(acc.y, nd, bb.y);
        r.z = fmaf(acc.z, nd, bb.z);
        r.w = fmaf(acc.w, nd, bb.w);
        if (ACT) { r.x = tanhf(r.x); r.y = tanhf(r.y);
                   r.z = tanhf(r.z); r.w = tanhf(r.w); }
        if (TOX) {
            float ps = g_norm_src[gw];
            __half2 p0 = __floats2half2_rn(r.x * ps, r.y * ps);
            __half2 p1 = __floats2half2_rn(r.z * ps, r.w * ps);
            *(uint2*)&g_xa[(size_t)gw * 128 + lane * 4] =
                make_uint2(*(unsigned*)&p0, *(unsigned*)&p1);
        } else {
            *(float4*)&outExt[(size_t)gw * 128 + lane * 4] = r;
        }
    } else {
        float2 bb = *(const float2*)&bias[lane * 2];
        float2 r;
        r.x = fmaf(acc.x, nd, bb.x);
        r.y = fmaf(acc.y, nd, bb.y);
        if (ACT) { r.x = tanhf(r.x); r.y = tanhf(r.y); }
        *(float2*)&outExt[(size_t)gw * 64 + lane * 2] = r;
    }
}

// ---------------- launch ----------------------------------------------------

extern "C" void kernel_launch(void* const* d_in, const int* in_sizes, int n_in,
                              void* d_out, int out_size)
{
    const float* feat = (const float*)d_in[0];
    const void*  ei   = d_in[1];
    const float* W0 = (const float*)d_in[2]; const float* b0 = (const float*)d_in[3];
    const float* W1 = (const float*)d_in[4]; const float* b1 = (const float*)d_in[5];
    const float* W2 = (const float*)d_in[6]; const float* b2 = (const float*)d_in[7];
    const float* W3 = (const float*)d_in[8]; const float* b3 = (const float*)d_in[9];

    int N = in_sizes[0] / 128;
    int E = in_sizes[1] / 2;
    float* out = (float*)d_out;

    int nodeBlocks = (N + 255) / 256;
    int wBlocks = (57344 + 255) / 256;

    k_zero     <<<nodeBlocks + wBlocks, 256>>>(ei, E, N, W0, W1, W2, W3);
    k_degree   <<<(E + 255) / 256, 256>>>(ei, E);
    k_scan_norm<<<(N + 1023) / 1024, 1024>>>(N);

    int gemmGrid = (N + 127) / 128;
    int aggGrid  = (N * 32 + 255) / 256;

    // #4: layer-0 GEMM (profiled launch) — converts fp32 feat at staging
    k_gemm_mma<128, true><<<gemmGrid, 256>>>(feat, 0, N);

    // #5,#6: finish CSR (only k_agg needs it)
    k_scan_add<<<(N + 255) / 256, 256>>>(N, E);
    k_fill    <<<(E + 255) / 256, 256>>>(ei, E);

    // remaining layers: agg emits prescaled fp16 X; gemm copies it straight in
    k_agg<128, true, true ><<<aggGrid, 256>>>(b0, nullptr, N);
    k_gemm_mma<128, false><<<gemmGrid, 256>>>(nullptr, 16384, N);
    k_agg<128, true, true ><<<aggGrid, 256>>>(b1, nullptr, N);
    k_gemm_mma<128, false><<<gemmGrid, 256>>>(nullptr, 32768, N);
    k_agg<128, true, true ><<<aggGrid, 256>>>(b2, nullptr, N);
    k_gemm_mma<64, false><<<gemmGrid, 256>>>(nullptr, 49152, N);
    k_agg<64, false, false><<<aggGrid, 256>>>(b3, out, N);
}

// round 14
// speedup vs baseline: 1.1835x; 1.0021x over previous
#include <cuda_runtime.h>
#include <cuda_bf16.h>
#include <cuda_fp16.h>
#include <mma.h>
#include <math.h>

using namespace nvcuda;

#define NMAX 100000
#define EMAX 1600000

// ---------------- static device scratch ------------------------------------
__device__ __align__(16) __half g_xa[NMAX * 128];     // fp16 X (prescaled), layers 1-3
__device__ __align__(16) __half g_bufH[NMAX * 128];   // fp16 GEMM output H (gather source)
__device__ int   g_col[EMAX];
__device__ int   g_rowptr[NMAX + 1];
__device__ int   g_cursor[NMAX];
__device__ int   g_outdeg[NMAX];
__device__ int   g_indeg[NMAX];
__device__ float g_norm_src[NMAX];
__device__ float g_norm_dst[NMAX];
__device__ int   g_bsums[128];
__device__ int   g_is64;
// W split fp16 hi/lo, transposed to [n][k], bases 0/16384/32768/49152
__device__ __align__(16) __half g_wt_hi[57344];
__device__ __align__(16) __half g_wt_lo[57344];

// ---------------- preprocessing ---------------------------------------------

__global__ void k_zero(const void* ei, int E, int n,
                       const float* __restrict__ W0, const float* __restrict__ W1,
                       const float* __restrict__ W2, const float* __restrict__ W3)
{
    int nodeBlocks = (n + 255) >> 8;
    int b = blockIdx.x;
    if (b < nodeBlocks) {
        int i = b * 256 + threadIdx.x;
        if (i < n) { g_outdeg[i] = 0; g_indeg[i] = 0; }
        if (b == 0 && threadIdx.x == 0) {
            const unsigned long long* p = (const unsigned long long*)ei;
            int cnt = E < 256 ? E : 256;
            int nz = 0;
            for (int k = 0; k < cnt; k++)
                if ((p[k] >> 32) != 0ULL) nz++;
            g_is64 = (nz == 0) ? 1 : 0;
        }
    } else {
        int id = (b - nodeBlocks) * 256 + threadIdx.x;
        float w; int dst;
        if (id < 49152) {
            int layer = id >> 14;
            int rem = id & 16383;
            int k = rem >> 7, nn = rem & 127;
            const float* W = layer == 0 ? W0 : (layer == 1 ? W1 : W2);
            w = W[rem];
            dst = layer * 16384 + nn * 128 + k;
        } else if (id < 57344) {
            int rem = id - 49152;
            int k = rem >> 6, nn = rem & 63;
            w = W3[rem];
            dst = 49152 + nn * 128 + k;
        } else return;
        __half h = __float2half(w);
        g_wt_hi[dst] = h;
        g_wt_lo[dst] = __float2half(w - __half2float(h));
    }
}

__device__ __forceinline__ int edge_at(const void* ei, int E, int which, int e) {
    if (g_is64) return (int)((const long long*)ei)[(size_t)which * E + e];
    return ((const int*)ei)[which * E + e];
}

__global__ void k_degree(const void* __restrict__ ei, int E) {
    int e = blockIdx.x * blockDim.x + threadIdx.x;
    if (e < E) {
        atomicAdd(&g_outdeg[edge_at(ei, E, 0, e)], 1);
        atomicAdd(&g_indeg[edge_at(ei, E, 1, e)], 1);
    }
}

__global__ void k_scan_norm(int n) {
    __shared__ int s[2][1024];
    int t = threadIdx.x;
    int i = blockIdx.x * 1024 + t;
    int v = (i < n) ? g_indeg[i] : 0;
    s[0][t] = v;
    __syncthreads();
    int pin = 0;
    #pragma unroll
    for (int off = 1; off < 1024; off <<= 1) {
        int po = pin ^ 1;
        int val = s[pin][t];
        if (t >= off) val += s[pin][t - off];
        s[po][t] = val;
        __syncthreads();
        pin = po;
    }
    int incl = s[pin][t];
    if (i < n) g_rowptr[i] = incl - v;
    if (t == 1023) g_bsums[blockIdx.x] = incl;
    if (i < n) {
        int od = g_outdeg[i];
        g_norm_src[i] = od > 0 ? rsqrtf((float)od) : 0.0f;
        g_norm_dst[i] = v  > 0 ? rsqrtf((float)v)  : 0.0f;
    }
}

__global__ void k_scan_add(int n, int E) {
    __shared__ int s_off;
    int i = blockIdx.x * blockDim.x + threadIdx.x;
    if (threadIdx.x == 0) {
        int b = (blockIdx.x * blockDim.x) >> 10;
        int off = 0;
        for (int k = 0; k < b; k++) off += g_bsums[k];
        s_off = off;
    }
    __syncthreads();
    if (i < n) {
        int r = g_rowptr[i] + s_off;
        g_rowptr[i] = r;
        g_cursor[i] = r;
    }
    if (i == 0) g_rowptr[n] = E;
}

__global__ void k_fill(const void* __restrict__ ei, int E) {
    int e = blockIdx.x * blockDim.x + threadIdx.x;
    if (e < E) {
        int d = edge_at(ei, E, 1, e);
        int pos = atomicAdd(&g_cursor[d], 1);
        g_col[pos] = edge_at(ei, E, 0, e);
    }
}

// ---------------- tensor-core GEMM: H(fp16) = A @ (Wh + Wl) ------------------
// (R13 configuration — unchanged, validated best)
template <int DOUT, bool CONV>
__global__ void __launch_bounds__(256, 2) k_gemm_mma(
    const float* __restrict__ Xext, int wtBase, int n)
{
    __half* __restrict__ H = g_bufH;

    constexpr int WN = DOUT / 32;
    constexpr int AS = 40;
    __shared__ __align__(16) __half Ax[128 * AS];
    __shared__ __align__(16) __half Bh[DOUT * AS];
    __shared__ __align__(16) __half Bl[DOUT * AS];
    __shared__ __align__(16) float Stage[8 * 256];

    int tid  = threadIdx.x;
    int lane = tid & 31;
    int wrp  = tid >> 5;
    int warp_m = wrp >> 1;
    int warp_n = wrp & 1;
    int rows0 = blockIdx.x * 128;

    wmma::fragment<wmma::matrix_a, 16, 16, 16, __half, wmma::row_major> fa[2];
    wmma::fragment<wmma::matrix_b, 16, 16, 16, __half, wmma::col_major> fb_hi, fb_lo;
    wmma::fragment<wmma::accumulator, 16, 16, 16, float> facc[2][WN];
    #pragma unroll
    for (int fm = 0; fm < 2; fm++)
        #pragma unroll
        for (int fn = 0; fn < WN; fn++) wmma::fill_fragment(facc[fm][fn], 0.0f);

    const __half* gh = g_wt_hi + wtBase;
    const __half* gl = g_wt_lo + wtBase;

    for (int kc = 0; kc < 128; kc += 32) {
        if (CONV) {
            #pragma unroll
            for (int u = 0; u < 4; u++) {
                int q = tid + 256 * u;
                int row = q >> 3;
                int kq = q & 7;
                int grow = rows0 + row;
                float4 v = make_float4(0.f, 0.f, 0.f, 0.f);
                float ns = 0.f;
                if (grow < n) {
                    ns = g_norm_src[grow];
                    v = *(const float4*)&Xext[(size_t)grow * 128 + kc + kq * 4];
                }
                __half2 p0 = __floats2half2_rn(v.x * ns, v.y * ns);
                __half2 p1 = __floats2half2_rn(v.z * ns, v.w * ns);
                *(uint2*)&Ax[row * AS + kq * 4] =
                    make_uint2(*(unsigned*)&p0, *(unsigned*)&p1);
            }
        } else {
            #pragma unroll
            for (int u = 0; u < 2; u++) {
                int q = tid + 256 * u;
                int row = q >> 2;
                int kq = q & 3;
                int grow = rows0 + row;
                uint4 v = make_uint4(0u, 0u, 0u, 0u);
                if (grow < n)
                    v = *(const uint4*)&g_xa[(size_t)grow * 128 + kc + kq * 8];
                *(uint4*)&Ax[row * AS + kq * 8] = v;
            }
        }
        for (int q = tid; q < DOUT * 16; q += 256) {
            int rn = q >> 4;
            int k2 = q & 15;
            ((unsigned*)Bh)[rn * (AS / 2) + k2] = ((const unsigned*)gh)[rn * 64 + (kc >> 1) + k2];
            ((unsigned*)Bl)[rn * (AS / 2) + k2] = ((const unsigned*)gl)[rn * 64 + (kc >> 1) + k2];
        }
        __syncthreads();

        #pragma unroll
        for (int kk = 0; kk < 32; kk += 16) {
            #pragma unroll
            for (int fm = 0; fm < 2; fm++)
                wmma::load_matrix_sync(fa[fm], &Ax[(warp_m * 32 + fm * 16) * AS + kk], AS);
            #pragma unroll
            for (int fn = 0; fn < WN; fn++) {
                int nb = (warp_n * (DOUT / 2) + fn * 16) * AS + kk;
                wmma::load_matrix_sync(fb_hi, &Bh[nb], AS);
                wmma::load_matrix_sync(fb_lo, &Bl[nb], AS);
                #pragma unroll
                for (int fm = 0; fm < 2; fm++) {
                    wmma::mma_sync(facc[fm][fn], fa[fm], fb_hi, facc[fm][fn]);
                    wmma::mma_sync(facc[fm][fn], fa[fm], fb_lo, facc[fm][fn]);
                }
            }
        }
        __syncthreads();
    }

    float* st = &Stage[wrp * 256];
    #pragma unroll
    for (int fm = 0; fm < 2; fm++)
        #pragma unroll
        for (int fn = 0; fn < WN; fn++) {
            wmma::store_matrix_sync(st, facc[fm][fn], 16, wmma::mem_row_major);
            __syncwarp();
            int rbase = rows0 + warp_m * 32 + fm * 16;
            int cbase = warp_n * (DOUT / 2) + fn * 16;
            #pragma unroll
            for (int q = lane; q < 128; q += 32) {
                int r = q >> 3, c2 = q & 7;
                int gr = rbase + r;
                if (gr < n) {
                    __half2 hv = __floats2half2_rn(st[r * 16 + c2 * 2],
                                                   st[r * 16 + c2 * 2 + 1]);
                    *(__half2*)&H[(size_t)gr * DOUT + cbase + c2 * 2] = hv;
                }
            }
            __syncwarp();
        }
}

// ---------------- sparse aggregation: wide-gather variant --------------------
// One warp per dst node. LDG.128 gathers: warp splits into NB neighbor groups,
// each group of 32/NB lanes loads one full 16B-per-lane row slice.
//   D=128: NB=2 (16 lanes x 16B = 256B row), fold shfl_xor(16)
//   D=64 : NB=4 ( 8 lanes x 16B = 128B row), fold shfl_xor(8), shfl_xor(16)
// Each lane accumulates 8 columns in fp32; post-fold lanes redistribute.
template <int D, bool ACT, bool TOX>
__global__ void __launch_bounds__(256) k_agg(
    const float* __restrict__ bias, float* __restrict__ outExt, int n)
{
    const __half* __restrict__ H = g_bufH;

    int gw = (blockIdx.x * blockDim.x + threadIdx.x) >> 5;
    int lane = threadIdx.x & 31;
    if (gw >= n) return;

    constexpr int NB  = (D == 128) ? 2 : 4;     // neighbors per LDG round
    constexpr int LPG = 32 / NB;                // lanes per neighbor group
    int par = lane / LPG;                       // neighbor-parity group (0..NB-1)
    int cg  = lane % LPG;                       // column group (8 cols each)

    int beg = g_rowptr[gw];
    int end = g_rowptr[gw + 1];
    float acc[8];
    #pragma unroll
    for (int k = 0; k < 8; k++) acc[k] = 0.0f;

    for (int e = beg; e < end; e += 32) {
        int m = end - e; if (m > 32) m = 32;
        int idx = (lane < m) ? g_col[e + lane] : 0;
        int j = 0;
        for (; j + NB <= m; j += NB) {
            int s = __shfl_sync(0xffffffffu, idx, j + par);
            uint4 raw = *(const uint4*)&H[(size_t)s * D + cg * 8];
            const __half2* hp = (const __half2*)&raw;
            #pragma unroll
            for (int k = 0; k < 4; k++) {
                float2 f = __half22float2(hp[k]);
                acc[2 * k]     += f.x;
                acc[2 * k + 1] += f.y;
            }
        }
        if (j < m) {
            int rem = m - j;
            int src = j + par; if (src > 31) src = 31;
            int s = __shfl_sync(0xffffffffu, idx, src);
            if (par < rem) {
                uint4 raw = *(const uint4*)&H[(size_t)s * D + cg * 8];
                const __half2* hp = (const __half2*)&raw;
                #pragma unroll
                for (int k = 0; k < 4; k++) {
                    float2 f = __half22float2(hp[k]);
                    acc[2 * k]     += f.x;
                    acc[2 * k + 1] += f.y;
                }
            }
        }
    }

    // fold partial sums across neighbor groups
    if (D == 64) {
        #pragma unroll
        for (int k = 0; k < 8; k++)
            acc[k] += __shfl_xor_sync(0xffffffffu, acc[k], 8);
    }
    #pragma unroll
    for (int k = 0; k < 8; k++)
        acc[k] += __shfl_xor_sync(0xffffffffu, acc[k], 16);

    float nd = g_norm_dst[gw];

    if (D == 128) {
        // lane (cg,par) handles cols cg*8 + par*4 .. +4, vals acc[par*4..]
        int base = cg * 8 + par * 4;
        float4 bb = *(const float4*)&bias[base];
        float4 r;
        r.x = fmaf(acc[par * 4 + 0], nd, bb.x);
        r.y = fmaf(acc[par * 4 + 1], nd, bb.y);
        r.z = fmaf(acc[par * 4 + 2], nd, bb.z);
        r.w = fmaf(acc[par * 4 + 3], nd, bb.w);
        if (ACT) { r.x = tanhf(r.x); r.y = tanhf(r.y);
                   r.z = tanhf(r.z); r.w = tanhf(r.w); }
        if (TOX) {
            float ps = g_norm_src[gw];
            __half2 p0 = __floats2half2_rn(r.x * ps, r.y * ps);
            __half2 p1 = __floats2half2_rn(r.z * ps, r.w * ps);
            *(uint2*)&g_xa[(size_t)gw * 128 + base] =
                make_uint2(*(unsigned*)&p0, *(unsigned*)&p1);
        } else {
            *(float4*)&outExt[(size_t)gw * 128 + base] = r;
        }
    } else {
        // lane (cg,par) handles cols cg*8 + par*2 .. +2, vals acc[par*2..]
        int base = cg * 8 + par * 2;
        float2 bb = *(const float2*)&bias[base];
        float2 r;
        r.x = fmaf(acc[par * 2 + 0], nd, bb.x);
        r.y = fmaf(acc[par * 2 + 1], nd, bb.y);
        if (ACT) { r.x = tanhf(r.x); r.y = tanhf(r.y); }
        *(float2*)&outExt[(size_t)gw * 64 + base] = r;
    }
}

// ---------------- launch ----------------------------------------------------

extern "C" void kernel_launch(void* const* d_in, const int* in_sizes, int n_in,
                              void* d_out, int out_size)
{
    const float* feat = (const float*)d_in[0];
    const void*  ei   = d_in[1];
    const float* W0 = (const float*)d_in[2]; const float* b0 = (const float*)d_in[3];
    const float* W1 = (const float*)d_in[4]; const float* b1 = (const float*)d_in[5];
    const float* W2 = (const float*)d_in[6]; const float* b2 = (const float*)d_in[7];
    const float* W3 = (const float*)d_in[8]; const float* b3 = (const float*)d_in[9];

    int N = in_sizes[0] / 128;
    int E = in_sizes[1] / 2;
    float* out = (float*)d_out;

    int nodeBlocks = (N + 255) / 256;
    int wBlocks = (57344 + 255) / 256;

    k_zero     <<<nodeBlocks + wBlocks, 256>>>(ei, E, N, W0, W1, W2, W3);
    k_degree   <<<(E + 255) / 256, 256>>>(ei, E);
    k_scan_norm<<<(N + 1023) / 1024, 1024>>>(N);

    int gemmGrid = (N + 127) / 128;
    int aggGrid  = (N * 32 + 255) / 256;

    // #4: layer-0 GEMM (profiled launch)
    k_gemm_mma<128, true><<<gemmGrid, 256>>>(feat, 0, N);

    // #5,#6: finish CSR (only k_agg needs it)
    k_scan_add<<<(N + 255) / 256, 256>>>(N, E);
    k_fill    <<<(E + 255) / 256, 256>>>(ei, E);

    // remaining layers
    k_agg<128, true, true ><<<aggGrid, 256>>>(b0, nullptr, N);
    k_gemm_mma<128, false><<<gemmGrid, 256>>>(nullptr, 16384, N);
    k_agg<128, true, true ><<<aggGrid, 256>>>(b1, nullptr, N);
    k_gemm_mma<128, false><<<gemmGrid, 256>>>(nullptr, 32768, N);
    k_agg<128, true, true ><<<aggGrid, 256>>>(b2, nullptr, N);
    k_gemm_mma<64, false><<<gemmGrid, 256>>>(nullptr, 49152, N);
    k_agg<64, false, false><<<aggGrid, 256>>>(b3, out, N);
}

// round 15
// speedup vs baseline: 1.2828x; 1.0839x over previous
#include <cuda_runtime.h>
#include <cuda_bf16.h>
#include <cuda_fp16.h>
#include <mma.h>
#include <math.h>

using namespace nvcuda;

#define NMAX 100000
#define EMAX 1600000

// ---------------- static device scratch ------------------------------------
__device__ __align__(16) __half g_xa[NMAX * 128];     // fp16 X (prescaled), layers 1-3
__device__ __align__(16) __half g_bufH[NMAX * 128];   // fp16 GEMM output H (gather source)
__device__ int   g_col[EMAX];
__device__ int   g_rowptr[NMAX + 1];
__device__ int   g_cursor[NMAX];
__device__ int   g_outdeg[NMAX];
__device__ int   g_indeg[NMAX];
__device__ float g_norm_src[NMAX];
__device__ float g_norm_dst[NMAX];
__device__ int   g_bsums[128];
__device__ int   g_is64;
// W fp16 (RN), transposed to [n][k], bases 0/16384/32768/49152
__device__ __align__(16) __half g_wt[57344];

// ---------------- preprocessing ---------------------------------------------

__global__ void k_zero(const void* ei, int E, int n,
                       const float* __restrict__ W0, const float* __restrict__ W1,
                       const float* __restrict__ W2, const float* __restrict__ W3)
{
    int nodeBlocks = (n + 255) >> 8;
    int b = blockIdx.x;
    if (b < nodeBlocks) {
        int i = b * 256 + threadIdx.x;
        if (i < n) { g_outdeg[i] = 0; g_indeg[i] = 0; }
        if (b == 0 && threadIdx.x == 0) {
            const unsigned long long* p = (const unsigned long long*)ei;
            int cnt = E < 256 ? E : 256;
            int nz = 0;
            for (int k = 0; k < cnt; k++)
                if ((p[k] >> 32) != 0ULL) nz++;
            g_is64 = (nz == 0) ? 1 : 0;
        }
    } else {
        int id = (b - nodeBlocks) * 256 + threadIdx.x;
        float w; int dst;
        if (id < 49152) {
            int layer = id >> 14;
            int rem = id & 16383;
            int k = rem >> 7, nn = rem & 127;
            const float* W = layer == 0 ? W0 : (layer == 1 ? W1 : W2);
            w = W[rem];
            dst = layer * 16384 + nn * 128 + k;
        } else if (id < 57344) {
            int rem = id - 49152;
            int k = rem >> 6, nn = rem & 63;
            w = W3[rem];
            dst = 49152 + nn * 128 + k;
        } else return;
        g_wt[dst] = __float2half(w);
    }
}

__device__ __forceinline__ int edge_at(const void* ei, int E, int which, int e) {
    if (g_is64) return (int)((const long long*)ei)[(size_t)which * E + e];
    return ((const int*)ei)[which * E + e];
}

__global__ void k_degree(const void* __restrict__ ei, int E) {
    int e = blockIdx.x * blockDim.x + threadIdx.x;
    if (e < E) {
        atomicAdd(&g_outdeg[edge_at(ei, E, 0, e)], 1);
        atomicAdd(&g_indeg[edge_at(ei, E, 1, e)], 1);
    }
}

__global__ void k_scan_norm(int n) {
    __shared__ int s[2][1024];
    int t = threadIdx.x;
    int i = blockIdx.x * 1024 + t;
    int v = (i < n) ? g_indeg[i] : 0;
    s[0][t] = v;
    __syncthreads();
    int pin = 0;
    #pragma unroll
    for (int off = 1; off < 1024; off <<= 1) {
        int po = pin ^ 1;
        int val = s[pin][t];
        if (t >= off) val += s[pin][t - off];
        s[po][t] = val;
        __syncthreads();
        pin = po;
    }
    int incl = s[pin][t];
    if (i < n) g_rowptr[i] = incl - v;
    if (t == 1023) g_bsums[blockIdx.x] = incl;
    if (i < n) {
        int od = g_outdeg[i];
        g_norm_src[i] = od > 0 ? rsqrtf((float)od) : 0.0f;
        g_norm_dst[i] = v  > 0 ? rsqrtf((float)v)  : 0.0f;
    }
}

__global__ void k_scan_add(int n, int E) {
    __shared__ int s_off;
    int i = blockIdx.x * blockDim.x + threadIdx.x;
    if (threadIdx.x == 0) {
        int b = (blockIdx.x * blockDim.x) >> 10;
        int off = 0;
        for (int k = 0; k < b; k++) off += g_bsums[k];
        s_off = off;
    }
    __syncthreads();
    if (i < n) {
        int r = g_rowptr[i] + s_off;
        g_rowptr[i] = r;
        g_cursor[i] = r;
    }
    if (i == 0) g_rowptr[n] = E;
}

__global__ void k_fill(const void* __restrict__ ei, int E) {
    int e = blockIdx.x * blockDim.x + threadIdx.x;
    if (e < E) {
        int d = edge_at(ei, E, 1, e);
        int pos = atomicAdd(&g_cursor[d], 1);
        g_col[pos] = edge_at(ei, E, 0, e);
    }
}

// ---------------- tensor-core GEMM: H(fp16) = A @ W(fp16) --------------------
// Single-product fp16 GEMM (W stored RN fp16). Block tile 128 x DOUT,
// 8 warps = 4(M) x 2(N), padded smem stride 40, 2 blocks/SM.
template <int DOUT, bool CONV>
__global__ void __launch_bounds__(256, 2) k_gemm_mma(
    const float* __restrict__ Xext, int wtBase, int n)
{
    __half* __restrict__ H = g_bufH;

    constexpr int WN = DOUT / 32;
    constexpr int AS = 40;
    __shared__ __align__(16) __half Ax[128 * AS];
    __shared__ __align__(16) __half Bs[DOUT * AS];
    __shared__ __align__(16) float Stage[8 * 256];

    int tid  = threadIdx.x;
    int lane = tid & 31;
    int wrp  = tid >> 5;
    int warp_m = wrp >> 1;
    int warp_n = wrp & 1;
    int rows0 = blockIdx.x * 128;

    wmma::fragment<wmma::matrix_a, 16, 16, 16, __half, wmma::row_major> fa[2];
    wmma::fragment<wmma::matrix_b, 16, 16, 16, __half, wmma::col_major> fb;
    wmma::fragment<wmma::accumulator, 16, 16, 16, float> facc[2][WN];
    #pragma unroll
    for (int fm = 0; fm < 2; fm++)
        #pragma unroll
        for (int fn = 0; fn < WN; fn++) wmma::fill_fragment(facc[fm][fn], 0.0f);

    const __half* gw = g_wt + wtBase;

    for (int kc = 0; kc < 128; kc += 32) {
        if (CONV) {
            #pragma unroll
            for (int u = 0; u < 4; u++) {
                int q = tid + 256 * u;
                int row = q >> 3;
                int kq = q & 7;
                int grow = rows0 + row;
                float4 v = make_float4(0.f, 0.f, 0.f, 0.f);
                float ns = 0.f;
                if (grow < n) {
                    ns = g_norm_src[grow];
                    v = *(const float4*)&Xext[(size_t)grow * 128 + kc + kq * 4];
                }
                __half2 p0 = __floats2half2_rn(v.x * ns, v.y * ns);
                __half2 p1 = __floats2half2_rn(v.z * ns, v.w * ns);
                *(uint2*)&Ax[row * AS + kq * 4] =
                    make_uint2(*(unsigned*)&p0, *(unsigned*)&p1);
            }
        } else {
            #pragma unroll
            for (int u = 0; u < 2; u++) {
                int q = tid + 256 * u;
                int row = q >> 2;
                int kq = q & 3;
                int grow = rows0 + row;
                uint4 v = make_uint4(0u, 0u, 0u, 0u);
                if (grow < n)
                    v = *(const uint4*)&g_xa[(size_t)grow * 128 + kc + kq * 8];
                *(uint4*)&Ax[row * AS + kq * 8] = v;
            }
        }
        // stage B (4B copies of pre-transposed fp16 W)
        for (int q = tid; q < DOUT * 16; q += 256) {
            int rn = q >> 4;
            int k2 = q & 15;
            ((unsigned*)Bs)[rn * (AS / 2) + k2] = ((const unsigned*)gw)[rn * 64 + (kc >> 1) + k2];
        }
        __syncthreads();

        #pragma unroll
        for (int kk = 0; kk < 32; kk += 16) {
            #pragma unroll
            for (int fm = 0; fm < 2; fm++)
                wmma::load_matrix_sync(fa[fm], &Ax[(warp_m * 32 + fm * 16) * AS + kk], AS);
            #pragma unroll
            for (int fn = 0; fn < WN; fn++) {
                int nb = (warp_n * (DOUT / 2) + fn * 16) * AS + kk;
                wmma::load_matrix_sync(fb, &Bs[nb], AS);
                #pragma unroll
                for (int fm = 0; fm < 2; fm++)
                    wmma::mma_sync(facc[fm][fn], fa[fm], fb, facc[fm][fn]);
            }
        }
        __syncthreads();
    }

    float* st = &Stage[wrp * 256];
    #pragma unroll
    for (int fm = 0; fm < 2; fm++)
        #pragma unroll
        for (int fn = 0; fn < WN; fn++) {
            wmma::store_matrix_sync(st, facc[fm][fn], 16, wmma::mem_row_major);
            __syncwarp();
            int rbase = rows0 + warp_m * 32 + fm * 16;
            int cbase = warp_n * (DOUT / 2) + fn * 16;
            #pragma unroll
            for (int q = lane; q < 128; q += 32) {
                int r = q >> 3, c2 = q & 7;
                int gr = rbase + r;
                if (gr < n) {
                    __half2 hv = __floats2half2_rn(st[r * 16 + c2 * 2],
                                                   st[r * 16 + c2 * 2 + 1]);
                    *(__half2*)&H[(size_t)gr * DOUT + cbase + c2 * 2] = hv;
                }
            }
            __syncwarp();
        }
}

// ---------------- sparse aggregation: wide-gather (R14, at LTS floor) -------
template <int D, bool ACT, bool TOX>
__global__ void __launch_bounds__(256) k_agg(
    const float* __restrict__ bias, float* __restrict__ outExt, int n)
{
    const __half* __restrict__ H = g_bufH;

    int gw = (blockIdx.x * blockDim.x + threadIdx.x) >> 5;
    int lane = threadIdx.x & 31;
    if (gw >= n) return;

    constexpr int NB  = (D == 128) ? 2 : 4;
    constexpr int LPG = 32 / NB;
    int par = lane / LPG;
    int cg  = lane % LPG;

    int beg = g_rowptr[gw];
    int end = g_rowptr[gw + 1];
    float acc[8];
    #pragma unroll
    for (int k = 0; k < 8; k++) acc[k] = 0.0f;

    for (int e = beg; e < end; e += 32) {
        int m = end - e; if (m > 32) m = 32;
        int idx = (lane < m) ? g_col[e + lane] : 0;
        int j = 0;
        for (; j + NB <= m; j += NB) {
            int s = __shfl_sync(0xffffffffu, idx, j + par);
            uint4 raw = *(const uint4*)&H[(size_t)s * D + cg * 8];
            const __half2* hp = (const __half2*)&raw;
            #pragma unroll
            for (int k = 0; k < 4; k++) {
                float2 f = __half22float2(hp[k]);
                acc[2 * k]     += f.x;
                acc[2 * k + 1] += f.y;
            }
        }
        if (j < m) {
            int rem = m - j;
            int src = j + par; if (src > 31) src = 31;
            int s = __shfl_sync(0xffffffffu, idx, src);
            if (par < rem) {
                uint4 raw = *(const uint4*)&H[(size_t)s * D + cg * 8];
                const __half2* hp = (const __half2*)&raw;
                #pragma unroll
                for (int k = 0; k < 4; k++) {
                    float2 f = __half22float2(hp[k]);
                    acc[2 * k]     += f.x;
                    acc[2 * k + 1] += f.y;
                }
            }
        }
    }

    if (D == 64) {
        #pragma unroll
        for (int k = 0; k < 8; k++)
            acc[k] += __shfl_xor_sync(0xffffffffu, acc[k], 8);
    }
    #pragma unroll
    for (int k = 0; k < 8; k++)
        acc[k] += __shfl_xor_sync(0xffffffffu, acc[k], 16);

    float nd = g_norm_dst[gw];

    if (D == 128) {
        int base = cg * 8 + par * 4;
        float4 bb = *(const float4*)&bias[base];
        float4 r;
        r.x = fmaf(acc[par * 4 + 0], nd, bb.x);
        r.y = fmaf(acc[par * 4 + 1], nd, bb.y);
        r.z = fmaf(acc[par * 4 + 2], nd, bb.z);
        r.w = fmaf(acc[par * 4 + 3], nd, bb.w);
        if (ACT) { r.x = tanhf(r.x); r.y = tanhf(r.y);
                   r.z = tanhf(r.z); r.w = tanhf(r.w); }
        if (TOX) {
            float ps = g_norm_src[gw];
            __half2 p0 = __floats2half2_rn(r.x * ps, r.y * ps);
            __half2 p1 = __floats2half2_rn(r.z * ps, r.w * ps);
            *(uint2*)&g_xa[(size_t)gw * 128 + base] =
                make_uint2(*(unsigned*)&p0, *(unsigned*)&p1);
        } else {
            *(float4*)&outExt[(size_t)gw * 128 + base] = r;
        }
    } else {
        int base = cg * 8 + par * 2;
        float2 bb = *(const float2*)&bias[base];
        float2 r;
        r.x = fmaf(acc[par * 2 + 0], nd, bb.x);
        r.y = fmaf(acc[par * 2 + 1], nd, bb.y);
        if (ACT) { r.x = tanhf(r.x); r.y = tanhf(r.y); }
        *(float2*)&outExt[(size_t)gw * 64 + base] = r;
    }
}

// ---------------- launch ----------------------------------------------------

extern "C" void kernel_launch(void* const* d_in, const int* in_sizes, int n_in,
                              void* d_out, int out_size)
{
    const float* feat = (const float*)d_in[0];
    const void*  ei   = d_in[1];
    const float* W0 = (const float*)d_in[2]; const float* b0 = (const float*)d_in[3];
    const float* W1 = (const float*)d_in[4]; const float* b1 = (const float*)d_in[5];
    const float* W2 = (const float*)d_in[6]; const float* b2 = (const float*)d_in[7];
    const float* W3 = (const float*)d_in[8]; const float* b3 = (const float*)d_in[9];

    int N = in_sizes[0] / 128;
    int E = in_sizes[1] / 2;
    float* out = (float*)d_out;

    int nodeBlocks = (N + 255) / 256;
    int wBlocks = (57344 + 255) / 256;

    k_zero     <<<nodeBlocks + wBlocks, 256>>>(ei, E, N, W0, W1, W2, W3);
    k_degree   <<<(E + 255) / 256, 256>>>(ei, E);
    k_scan_norm<<<(N + 1023) / 1024, 1024>>>(N);

    int gemmGrid = (N + 127) / 128;
    int aggGrid  = (N * 32 + 255) / 256;

    // #4: layer-0 GEMM (profiled launch)
    k_gemm_mma<128, true><<<gemmGrid, 256>>>(feat, 0, N);

    // #5,#6: finish CSR (only k_agg needs it)
    k_scan_add<<<(N + 255) / 256, 256>>>(N, E);
    k_fill    <<<(E + 255) / 256, 256>>>(ei, E);

    // remaining layers
    k_agg<128, true, true ><<<aggGrid, 256>>>(b0, nullptr, N);
    k_gemm_mma<128, false><<<gemmGrid, 256>>>(nullptr, 16384, N);
    k_agg<128, true, true ><<<aggGrid, 256>>>(b1, nullptr, N);
    k_gemm_mma<128, false><<<gemmGrid, 256>>>(nullptr, 32768, N);
    k_agg<128, true, true ><<<aggGrid, 256>>>(b2, nullptr, N);
    k_gemm_mma<64, false><<<gemmGrid, 256>>>(nullptr, 49152, N);
    k_agg<64, false, false><<<aggGrid, 256>>>(b3, out, N);
}

// round 16
// speedup vs baseline: 1.4142x; 1.1025x over previous
#include <cuda_runtime.h>
#include <cuda_bf16.h>
#include <cuda_fp16.h>
#include <mma.h>
#include <math.h>

using namespace nvcuda;

#define NMAX 100000
#define EMAX 1600000

// ---------------- static device scratch ------------------------------------
__device__ __align__(16) __half g_xa[NMAX * 128];     // fp16 X (prescaled), layers 1-3
__device__ __align__(16) __half g_bufH[NMAX * 128];   // fp16 GEMM output H (gather source)
__device__ int   g_col[EMAX];
__device__ int   g_rowptr[NMAX + 1];
__device__ int   g_cursor[NMAX];
__device__ int   g_outdeg[NMAX];
__device__ int   g_indeg[NMAX];
__device__ float g_norm_src[NMAX];
__device__ float g_norm_dst[NMAX];
__device__ int   g_bsums[128];
__device__ int   g_is64;
// W fp16 (RN), transposed to [n][k], bases 0/16384/32768/49152
__device__ __align__(16) __half g_wt[57344];

// ---------------- preprocessing ---------------------------------------------

__global__ void k_zero(const void* ei, int E, int n,
                       const float* __restrict__ W0, const float* __restrict__ W1,
                       const float* __restrict__ W2, const float* __restrict__ W3)
{
    int nodeBlocks = (n + 255) >> 8;
    int b = blockIdx.x;
    if (b < nodeBlocks) {
        int i = b * 256 + threadIdx.x;
        if (i < n) { g_outdeg[i] = 0; g_indeg[i] = 0; }
        if (b == 0 && threadIdx.x == 0) {
            const unsigned long long* p = (const unsigned long long*)ei;
            int cnt = E < 256 ? E : 256;
            int nz = 0;
            for (int k = 0; k < cnt; k++)
                if ((p[k] >> 32) != 0ULL) nz++;
            g_is64 = (nz == 0) ? 1 : 0;
        }
    } else {
        int id = (b - nodeBlocks) * 256 + threadIdx.x;
        float w; int dst;
        if (id < 49152) {
            int layer = id >> 14;
            int rem = id & 16383;
            int k = rem >> 7, nn = rem & 127;
            const float* W = layer == 0 ? W0 : (layer == 1 ? W1 : W2);
            w = W[rem];
            dst = layer * 16384 + nn * 128 + k;
        } else if (id < 57344) {
            int rem = id - 49152;
            int k = rem >> 6, nn = rem & 63;
            w = W3[rem];
            dst = 49152 + nn * 128 + k;
        } else return;
        g_wt[dst] = __float2half(w);
    }
}

__device__ __forceinline__ int edge_at(const void* ei, int E, int which, int e) {
    if (g_is64) return (int)((const long long*)ei)[(size_t)which * E + e];
    return ((const int*)ei)[which * E + e];
}

__global__ void k_degree(const void* __restrict__ ei, int E) {
    int e = blockIdx.x * blockDim.x + threadIdx.x;
    if (e < E) {
        atomicAdd(&g_outdeg[edge_at(ei, E, 0, e)], 1);
        atomicAdd(&g_indeg[edge_at(ei, E, 1, e)], 1);
    }
}

__global__ void k_scan_norm(int n) {
    __shared__ int s[2][1024];
    int t = threadIdx.x;
    int i = blockIdx.x * 1024 + t;
    int v = (i < n) ? g_indeg[i] : 0;
    s[0][t] = v;
    __syncthreads();
    int pin = 0;
    #pragma unroll
    for (int off = 1; off < 1024; off <<= 1) {
        int po = pin ^ 1;
        int val = s[pin][t];
        if (t >= off) val += s[pin][t - off];
        s[po][t] = val;
        __syncthreads();
        pin = po;
    }
    int incl = s[pin][t];
    if (i < n) g_rowptr[i] = incl - v;
    if (t == 1023) g_bsums[blockIdx.x] = incl;
    if (i < n) {
        int od = g_outdeg[i];
        g_norm_src[i] = od > 0 ? rsqrtf((float)od) : 0.0f;
        g_norm_dst[i] = v  > 0 ? rsqrtf((float)v)  : 0.0f;
    }
}

__global__ void k_scan_add(int n, int E) {
    __shared__ int s_off;
    int i = blockIdx.x * blockDim.x + threadIdx.x;
    if (threadIdx.x == 0) {
        int b = (blockIdx.x * blockDim.x) >> 10;
        int off = 0;
        for (int k = 0; k < b; k++) off += g_bsums[k];
        s_off = off;
    }
    __syncthreads();
    if (i < n) {
        int r = g_rowptr[i] + s_off;
        g_rowptr[i] = r;
        g_cursor[i] = r;
    }
    if (i == 0) g_rowptr[n] = E;
}

__global__ void k_fill(const void* __restrict__ ei, int E) {
    int e = blockIdx.x * blockDim.x + threadIdx.x;
    if (e < E) {
        int d = edge_at(ei, E, 1, e);
        int pos = atomicAdd(&g_cursor[d], 1);
        g_col[pos] = edge_at(ei, E, 0, e);
    }
}

// ---------------- tensor-core GEMM: H(fp16) = A @ W(fp16) --------------------
// Whole-tile staging: A (128x128) and B (DOUTx128) staged ONCE into smem,
// one barrier, then barrier-free LDSM+HMMA mainloop over all 8 k-steps.
// Padded stride 136 halves (272B) -> LDSM conflict-free. 2 blocks/SM.
template <int DOUT, bool CONV>
__global__ void __launch_bounds__(256, 2) k_gemm_mma(
    const float* __restrict__ Xext, int wtBase, int n)
{
    __half* __restrict__ H = g_bufH;

    constexpr int WN = DOUT / 32;
    constexpr int AS = 136;                     // padded row stride (halves)
    constexpr int A_ELEM = 128 * AS;
    constexpr int B_ELEM = DOUT * AS;

    extern __shared__ __align__(16) __half smem[];
    __half* Ax = smem;
    __half* Bs = smem + A_ELEM;
    float*  Stage = (float*)(smem + A_ELEM + B_ELEM);

    int tid  = threadIdx.x;
    int lane = tid & 31;
    int wrp  = tid >> 5;
    int warp_m = wrp >> 1;
    int warp_n = wrp & 1;
    int rows0 = blockIdx.x * 128;

    // ---- stage A (full 128x128 tile) ----
    if (CONV) {
        // 4096 float4 total -> 16 per thread
        #pragma unroll
        for (int u = 0; u < 16; u++) {
            int q = tid + 256 * u;
            int row = q >> 5;                   // 32 float4 per row
            int kq = q & 31;
            int grow = rows0 + row;
            float4 v = make_float4(0.f, 0.f, 0.f, 0.f);
            float ns = 0.f;
            if (grow < n) {
                ns = g_norm_src[grow];
                v = *(const float4*)&Xext[(size_t)grow * 128 + kq * 4];
            }
            __half2 p0 = __floats2half2_rn(v.x * ns, v.y * ns);
            __half2 p1 = __floats2half2_rn(v.z * ns, v.w * ns);
            *(uint2*)&Ax[row * AS + kq * 4] =
                make_uint2(*(unsigned*)&p0, *(unsigned*)&p1);
        }
    } else {
        // 2048 uint4 total -> 8 per thread
        #pragma unroll
        for (int u = 0; u < 8; u++) {
            int q = tid + 256 * u;
            int row = q >> 4;                   // 16 uint4 per row
            int kq = q & 15;
            int grow = rows0 + row;
            uint4 v = make_uint4(0u, 0u, 0u, 0u);
            if (grow < n)
                v = *(const uint4*)&g_xa[(size_t)grow * 128 + kq * 8];
            *(uint4*)&Ax[row * AS + kq * 8] = v;
        }
    }
    // ---- stage B (whole DOUTx128 weight tile) ----
    {
        const uint4* gw4 = (const uint4*)(g_wt + wtBase);
        #pragma unroll
        for (int q = tid; q < DOUT * 16; q += 256) {
            int rn = q >> 4;
            int k4 = q & 15;
            *(uint4*)&Bs[rn * AS + k4 * 8] = gw4[rn * 16 + k4];
        }
    }
    __syncthreads();

    // ---- barrier-free mainloop ----
    wmma::fragment<wmma::matrix_a, 16, 16, 16, __half, wmma::row_major> fa[2];
    wmma::fragment<wmma::matrix_b, 16, 16, 16, __half, wmma::col_major> fb;
    wmma::fragment<wmma::accumulator, 16, 16, 16, float> facc[2][WN];
    #pragma unroll
    for (int fm = 0; fm < 2; fm++)
        #pragma unroll
        for (int fn = 0; fn < WN; fn++) wmma::fill_fragment(facc[fm][fn], 0.0f);

    #pragma unroll
    for (int kk = 0; kk < 128; kk += 16) {
        #pragma unroll
        for (int fm = 0; fm < 2; fm++)
            wmma::load_matrix_sync(fa[fm], &Ax[(warp_m * 32 + fm * 16) * AS + kk], AS);
        #pragma unroll
        for (int fn = 0; fn < WN; fn++) {
            wmma::load_matrix_sync(fb, &Bs[(warp_n * (DOUT / 2) + fn * 16) * AS + kk], AS);
            #pragma unroll
            for (int fm = 0; fm < 2; fm++)
                wmma::mma_sync(facc[fm][fn], fa[fm], fb, facc[fm][fn]);
        }
    }

    // ---- epilogue: fp32 acc -> fp16 H via per-warp smem staging ----
    float* st = &Stage[wrp * 256];
    #pragma unroll
    for (int fm = 0; fm < 2; fm++)
        #pragma unroll
        for (int fn = 0; fn < WN; fn++) {
            wmma::store_matrix_sync(st, facc[fm][fn], 16, wmma::mem_row_major);
            __syncwarp();
            int rbase = rows0 + warp_m * 32 + fm * 16;
            int cbase = warp_n * (DOUT / 2) + fn * 16;
            #pragma unroll
            for (int q = lane; q < 128; q += 32) {
                int r = q >> 3, c2 = q & 7;
                int gr = rbase + r;
                if (gr < n) {
                    __half2 hv = __floats2half2_rn(st[r * 16 + c2 * 2],
                                                   st[r * 16 + c2 * 2 + 1]);
                    *(__half2*)&H[(size_t)gr * DOUT + cbase + c2 * 2] = hv;
                }
            }
            __syncwarp();
        }
}

// ---------------- sparse aggregation: wide-gather (at LTS floor) -------------
template <int D, bool ACT, bool TOX>
__global__ void __launch_bounds__(256) k_agg(
    const float* __restrict__ bias, float* __restrict__ outExt, int n)
{
    const __half* __restrict__ H = g_bufH;

    int gw = (blockIdx.x * blockDim.x + threadIdx.x) >> 5;
    int lane = threadIdx.x & 31;
    if (gw >= n) return;

    constexpr int NB  = (D == 128) ? 2 : 4;
    constexpr int LPG = 32 / NB;
    int par = lane / LPG;
    int cg  = lane % LPG;

    int beg = g_rowptr[gw];
    int end = g_rowptr[gw + 1];
    float acc[8];
    #pragma unroll
    for (int k = 0; k < 8; k++) acc[k] = 0.0f;

    for (int e = beg; e < end; e += 32) {
        int m = end - e; if (m > 32) m = 32;
        int idx = (lane < m) ? g_col[e + lane] : 0;
        int j = 0;
        for (; j + NB <= m; j += NB) {
            int s = __shfl_sync(0xffffffffu, idx, j + par);
            uint4 raw = *(const uint4*)&H[(size_t)s * D + cg * 8];
            const __half2* hp = (const __half2*)&raw;
            #pragma unroll
            for (int k = 0; k < 4; k++) {
                float2 f = __half22float2(hp[k]);
                acc[2 * k]     += f.x;
                acc[2 * k + 1] += f.y;
            }
        }
        if (j < m) {
            int rem = m - j;
            int src = j + par; if (src > 31) src = 31;
            int s = __shfl_sync(0xffffffffu, idx, src);
            if (par < rem) {
                uint4 raw = *(const uint4*)&H[(size_t)s * D + cg * 8];
                const __half2* hp = (const __half2*)&raw;
                #pragma unroll
                for (int k = 0; k < 4; k++) {
                    float2 f = __half22float2(hp[k]);
                    acc[2 * k]     += f.x;
                    acc[2 * k + 1] += f.y;
                }
            }
        }
    }

    if (D == 64) {
        #pragma unroll
        for (int k = 0; k < 8; k++)
            acc[k] += __shfl_xor_sync(0xffffffffu, acc[k], 8);
    }
    #pragma unroll
    for (int k = 0; k < 8; k++)
        acc[k] += __shfl_xor_sync(0xffffffffu, acc[k], 16);

    float nd = g_norm_dst[gw];

    if (D == 128) {
        int base = cg * 8 + par * 4;
        float4 bb = *(const float4*)&bias[base];
        float4 r;
        r.x = fmaf(acc[par * 4 + 0], nd, bb.x);
        r.y = fmaf(acc[par * 4 + 1], nd, bb.y);
        r.z = fmaf(acc[par * 4 + 2], nd, bb.z);
        r.w = fmaf(acc[par * 4 + 3], nd, bb.w);
        if (ACT) { r.x = tanhf(r.x); r.y = tanhf(r.y);
                   r.z = tanhf(r.z); r.w = tanhf(r.w); }
        if (TOX) {
            float ps = g_norm_src[gw];
            __half2 p0 = __floats2half2_rn(r.x * ps, r.y * ps);
            __half2 p1 = __floats2half2_rn(r.z * ps, r.w * ps);
            *(uint2*)&g_xa[(size_t)gw * 128 + base] =
                make_uint2(*(unsigned*)&p0, *(unsigned*)&p1);
        } else {
            *(float4*)&outExt[(size_t)gw * 128 + base] = r;
        }
    } else {
        int base = cg * 8 + par * 2;
        float2 bb = *(const float2*)&bias[base];
        float2 r;
        r.x = fmaf(acc[par * 2 + 0], nd, bb.x);
        r.y = fmaf(acc[par * 2 + 1], nd, bb.y);
        if (ACT) { r.x = tanhf(r.x); r.y = tanhf(r.y); }
        *(float2*)&outExt[(size_t)gw * 64 + base] = r;
    }
}

// ---------------- launch ----------------------------------------------------

extern "C" void kernel_launch(void* const* d_in, const int* in_sizes, int n_in,
                              void* d_out, int out_size)
{
    const float* feat = (const float*)d_in[0];
    const void*  ei   = d_in[1];
    const float* W0 = (const float*)d_in[2]; const float* b0 = (const float*)d_in[3];
    const float* W1 = (const float*)d_in[4]; const float* b1 = (const float*)d_in[5];
    const float* W2 = (const float*)d_in[6]; const float* b2 = (const float*)d_in[7];
    const float* W3 = (const float*)d_in[8]; const float* b3 = (const float*)d_in[9];

    int N = in_sizes[0] / 128;
    int E = in_sizes[1] / 2;
    float* out = (float*)d_out;

    // dynamic smem: A(128*136) + B(DOUT*136) halves + Stage 8KB
    const int smem128 = (128 * 136 + 128 * 136) * 2 + 8192;  // 77824
    const int smem64  = (128 * 136 +  64 * 136) * 2 + 8192;  // 60416
    cudaFuncSetAttribute(k_gemm_mma<128, true>,
        cudaFuncAttributeMaxDynamicSharedMemorySize, smem128);
    cudaFuncSetAttribute(k_gemm_mma<128, false>,
        cudaFuncAttributeMaxDynamicSharedMemorySize, smem128);
    cudaFuncSetAttribute(k_gemm_mma<64, false>,
        cudaFuncAttributeMaxDynamicSharedMemorySize, smem64);

    int nodeBlocks = (N + 255) / 256;
    int wBlocks = (57344 + 255) / 256;

    k_zero     <<<nodeBlocks + wBlocks, 256>>>(ei, E, N, W0, W1, W2, W3);
    k_degree   <<<(E + 255) / 256, 256>>>(ei, E);
    k_scan_norm<<<(N + 1023) / 1024, 1024>>>(N);

    int gemmGrid = (N + 127) / 128;
    int aggGrid  = (N * 32 + 255) / 256;

    // #4: layer-0 GEMM (profiled launch)
    k_gemm_mma<128, true><<<gemmGrid, 256, smem128>>>(feat, 0, N);

    // #5,#6: finish CSR (only k_agg needs it)
    k_scan_add<<<(N + 255) / 256, 256>>>(N, E);
    k_fill    <<<(E + 255) / 256, 256>>>(ei, E);

    // remaining layers
    k_agg<128, true, true ><<<aggGrid, 256>>>(b0, nullptr, N);
    k_gemm_mma<128, false><<<gemmGrid, 256, smem128>>>(nullptr, 16384, N);
    k_agg<128, true, true ><<<aggGrid, 256>>>(b1, nullptr, N);
    k_gemm_mma<128, false><<<gemmGrid, 256, smem128>>>(nullptr, 32768, N);
    k_agg<128, true, true ><<<aggGrid, 256>>>(b2, nullptr, N);
    k_gemm_mma<64, false><<<gemmGrid, 256, smem64>>>(nullptr, 49152, N);
    k_agg<64, false, false><<<aggGrid, 256>>>(b3, out, N);
}